// round 2
// baseline (speedup 1.0000x reference)
#include <cuda_runtime.h>
#include <cuda_bf16.h>
#include <cstdint>

// ---------------- scratch (device globals; no runtime allocation) ----------------
__device__ float g_x1[(size_t)8 * 1024 * 40 * 64];   // conv0 out [B,1024,40,64]
__device__ float g_x2[(size_t)8 * 512 * 20 * 64];    // conv1 out [B,512,20,64]
__device__ float g_p [(size_t)4096 * 32];            // proj out  [B*S,32]
__device__ float g_emb [(size_t)4096 * 256];         // primary caps [B*S,32,8]
__device__ float g_emb2[(size_t)4096 * 256];         // conv caps    [B*S,32,8]

// ---------------- helpers ----------------
__device__ __forceinline__ unsigned long long pack2(float x, float y) {
    unsigned long long r;
    asm("mov.b64 %0, {%1, %2};" : "=l"(r) : "f"(x), "f"(y));
    return r;
}
__device__ __forceinline__ void fma2(unsigned long long& c, unsigned long long a, unsigned long long b) {
    asm("fma.rn.f32x2 %0, %1, %2, %0;" : "+l"(c) : "l"(a), "l"(b));
}
__device__ __forceinline__ float2 unpack2(unsigned long long v) {
    float lo, hi;
    asm("mov.b64 {%0, %1}, %2;" : "=f"(lo), "=f"(hi) : "l"(v));
    return make_float2(lo, hi);
}

// block-wide sum of two values (blockDim.x == 256)
__device__ __forceinline__ void blockReduceSum2(float& a, float& b) {
    __shared__ float red[16];
    int lane = threadIdx.x & 31, w = threadIdx.x >> 5;
#pragma unroll
    for (int o = 16; o; o >>= 1) {
        a += __shfl_xor_sync(0xffffffffu, a, o);
        b += __shfl_xor_sync(0xffffffffu, b, o);
    }
    if (lane == 0) { red[w] = a; red[8 + w] = b; }
    __syncthreads();
    a = red[0] + red[1] + red[2] + red[3] + red[4] + red[5] + red[6] + red[7];
    b = red[8] + red[9] + red[10] + red[11] + red[12] + red[13] + red[14] + red[15];
    __syncthreads();
}

// ---------------- K1: conv0 maxout + time mask ----------------
// inputs [8,2048,80] -> g_x1 [8,1024,40,64]; SAME pad: lo=0, hi=1 both dims.
__global__ void __launch_bounds__(256) k_conv0(
    const float* __restrict__ in,
    const float* __restrict__ w1, const float* __restrict__ b1,
    const float* __restrict__ w2, const float* __restrict__ b2,
    const int* __restrict__ lens)
{
    __shared__ float sw1[576], sw2[576], sb[128];
    int tid = threadIdx.x;
    for (int i = tid; i < 576; i += 256) { sw1[i] = w1[i]; sw2[i] = w2[i]; }
    if (tid < 64) { sb[tid] = b1[tid]; sb[64 + tid] = b2[tid]; }
    __syncthreads();

    int idx = blockIdx.x * 256 + tid;
    int c = idx & 63;
    int t = idx >> 6;
    int ow = t % 40; t /= 40;
    int oh = t & 1023;
    int b  = t >> 10;

    int vl = (lens[b] + 1) >> 1;  // ceil(len/2)
    float out = 0.f;
    if (oh < vl) {
        float a1 = sb[c], a2 = sb[64 + c];
#pragma unroll
        for (int kh = 0; kh < 3; kh++) {
            int h = 2 * oh + kh;
            if (h < 2048) {
                const float* ir = in + ((size_t)b * 2048 + h) * 80;
#pragma unroll
                for (int kw = 0; kw < 3; kw++) {
                    int w = 2 * ow + kw;
                    if (w < 80) {
                        float v = ir[w];
                        int wi = (kh * 3 + kw) * 64 + c;
                        a1 = fmaf(v, sw1[wi], a1);
                        a2 = fmaf(v, sw2[wi], a2);
                    }
                }
            }
        }
        out = fmaxf(a1, a2);
    }
    g_x1[idx] = out;
}

// ---------------- K2: conv1 maxout + time mask (f32x2 packed over ic pairs) ----------------
// g_x1 [8,1024,40,64] -> g_x2 [8,512,20,64]. Block per (b, oh). SAME pad lo=0 hi=1.
__global__ void __launch_bounds__(256) k_conv1(
    const float* __restrict__ w1, const float* __restrict__ b1,
    const float* __restrict__ w2, const float* __restrict__ b2,
    const int* __restrict__ lens)
{
    __shared__ float sin_[3 * 40 * 64];  // 3 input rows, 30KB
    int tid = threadIdx.x;
    int b  = blockIdx.x >> 9;
    int oh = blockIdx.x & 511;

    for (int i = tid; i < 7680; i += 256) {
        int r = i / 2560, rem = i - r * 2560;
        int h = 2 * oh + r;
        sin_[i] = (h < 1024) ? g_x1[((size_t)b * 1024 + h) * 2560 + rem] : 0.f;
    }
    __syncthreads();

    int oc = tid & 63, wq = tid >> 6;  // wq: 0..3, each handles 5 output widths
    unsigned long long acc1[5], acc2[5];
#pragma unroll
    for (int q = 0; q < 5; q++) {
        acc1[q] = pack2(b1[oc], 0.f);
        acc2[q] = pack2(b2[oc], 0.f);
    }

#pragma unroll
    for (int kh = 0; kh < 3; kh++) {
#pragma unroll
        for (int kw = 0; kw < 3; kw++) {
            const float* wr1 = w1 + ((size_t)(kh * 3 + kw) * 64) * 64 + oc;
            const float* wr2 = w2 + ((size_t)(kh * 3 + kw) * 64) * 64 + oc;
            int off[5];
#pragma unroll
            for (int q = 0; q < 5; q++) {
                int w_in = 2 * (wq * 5 + q) + kw;
                off[q] = (w_in < 40) ? (kh * 40 + w_in) * 64 : -1;
            }
#pragma unroll 4
            for (int ic2 = 0; ic2 < 32; ic2++) {
                int ic = ic2 * 2;
                unsigned long long wp1 = pack2(wr1[(size_t)ic * 64], wr1[(size_t)(ic + 1) * 64]);
                unsigned long long wp2 = pack2(wr2[(size_t)ic * 64], wr2[(size_t)(ic + 1) * 64]);
#pragma unroll
                for (int q = 0; q < 5; q++) {
                    if (off[q] >= 0) {
                        unsigned long long vv =
                            *reinterpret_cast<const unsigned long long*>(&sin_[off[q] + ic]);
                        fma2(acc1[q], vv, wp1);
                        fma2(acc2[q], vv, wp2);
                    }
                }
            }
        }
    }

    int vl = (lens[b] + 3) >> 2;  // ceil(len/4)
    float mask = (oh < vl) ? 1.f : 0.f;
#pragma unroll
    for (int q = 0; q < 5; q++) {
        float2 f1 = unpack2(acc1[q]);
        float2 f2 = unpack2(acc2[q]);
        int ow = wq * 5 + q;
        g_x2[(((size_t)b * 512 + oh) * 20 + ow) * 64 + oc] =
            fmaxf(f1.x + f1.y, f2.x + f2.y) * mask;
    }
}

// ---------------- K3a: projection [B,S,1280] @ [1280,32] + bias ----------------
__global__ void __launch_bounds__(256) k_proj(const float* __restrict__ pw,
                                              const float* __restrict__ pb)
{
    __shared__ float sx[8 * 1280];  // 8 positions, 40KB
    int tid = threadIdx.x;
    int b  = blockIdx.x >> 6;
    int s0 = (blockIdx.x & 63) << 3;
    const float* src = &g_x2[((size_t)b * 512 + s0) * 1280];
    for (int i = tid; i < 10240; i += 256) sx[i] = src[i];
    __syncthreads();

    int col = tid & 31, sl = tid >> 5;
    float acc = pb[col];
    const float* xr = &sx[sl * 1280];
#pragma unroll 8
    for (int k = 0; k < 1280; k++) acc = fmaf(xr[k], pw[(size_t)k * 32 + col], acc);
    g_p[((size_t)b * 512 + s0 + sl) * 32 + col] = acc;
}

// ---------------- K3b: encoder conv maxout + mask + squash + layernorm ----------------
// g_p [B*S,32] viewed as [B,S,32,1], 3x3 SAME stride1 conv (pad 1/1) -> [B,S,32,8]
__global__ void __launch_bounds__(256) k_enc(
    const float* __restrict__ ew1, const float* __restrict__ eb1,
    const float* __restrict__ ew2, const float* __restrict__ eb2,
    const int* __restrict__ lens)
{
    __shared__ float sp[3][32];
    __shared__ float sw[2][9][8];
    __shared__ float sbb[16];
    int tid = threadIdx.x;
    int p = blockIdx.x;
    int b = p >> 9, s = p & 511;

    if (tid < 96) {
        int j = tid >> 5, ii = tid & 31;
        int si = s + j - 1;
        sp[j][ii] = ((unsigned)si < 512u) ? g_p[((size_t)b * 512 + si) * 32 + ii] : 0.f;
    }
    if (tid < 72) { sw[0][tid / 8][tid & 7] = ew1[tid]; sw[1][tid / 8][tid & 7] = ew2[tid]; }
    if (tid < 16) sbb[tid] = (tid < 8) ? eb1[tid] : eb2[tid - 8];
    __syncthreads();

    int i = tid >> 3, d = tid & 7;
    float a1 = sbb[d], a2 = sbb[8 + d];
#pragma unroll
    for (int kh = 0; kh < 3; kh++)
#pragma unroll
        for (int kw = 0; kw < 3; kw++) {
            int ii = i + kw - 1;
            if ((unsigned)ii < 32u) {
                float v = sp[kh][ii];
                a1 = fmaf(v, sw[0][kh * 3 + kw][d], a1);
                a2 = fmaf(v, sw[1][kh * 3 + kw][d], a2);
            }
        }
    float e = fmaxf(a1, a2);
    int vl = (lens[b] + 3) >> 2;
    if (s >= vl) e = 0.f;

    // squash over d (8-lane aligned groups)
    float sq = e * e;
    sq += __shfl_xor_sync(0xffffffffu, sq, 1);
    sq += __shfl_xor_sync(0xffffffffu, sq, 2);
    sq += __shfl_xor_sync(0xffffffffu, sq, 4);
    float es = e * (sq / (1.f + sq) * rsqrtf(sq + 1e-6f));

    // layernorm over 256
    float a = es, b2 = es * es;
    blockReduceSum2(a, b2);
    float mu = a * (1.f / 256.f);
    float var = b2 * (1.f / 256.f) - mu * mu;
    g_emb[(size_t)p * 256 + tid] = (es - mu) * rsqrtf(var + 1e-3f);
}

// ---------------- K4: fused u_hat + dynamic routing (+ epilogues) ----------------
// LAYER 0: src g_emb, W0[96,32,8,8], O=32, no mask  -> layernorm(256) -> g_emb2
// LAYER 1: src g_emb2, W1[96,31,8,8], O=31 (pad to lane 32 with -1e9), class-0 masked
//          -> layernorm(248) -> lengths -> layernorm(31) -> out
template <int LAYER>
__global__ void __launch_bounds__(256, 1) k_route(
    const float* __restrict__ Wt, const float* __restrict__ Bt,
    float* __restrict__ out_final)
{
    constexpr int O_REAL = LAYER ? 31 : 32;
    __shared__ float swin[96 * 8];
    __shared__ float sred[8 * 256];
    __shared__ float sv[256];
    __shared__ float slen[32];

    int tid = threadIdx.x;
    int p = blockIdx.x;
    int b = p >> 9, s = p & 511;
    const float* src = LAYER ? g_emb2 : g_emb;

    // windowed gather: win[j*32+i][k] = emb[b, s+j-1, i, k]
    for (int t = tid; t < 768; t += 256) {
        int j = t >> 8, rem = t & 255;
        int sn = s + j - 1;
        swin[t] = ((unsigned)sn < 512u) ? src[((size_t)b * 512 + sn) * 256 + rem] : 0.f;
    }
    __syncthreads();

    int w = tid >> 5, o = tid & 31;
    int oc = (o < O_REAL) ? o : (O_REAL - 1);  // clamp for safe loads; zero u after

    float uj[12][8];
    float bij[12];
#pragma unroll
    for (int jj = 0; jj < 12; jj++) {
        int i = w * 12 + jj;
        const float4* Wp = reinterpret_cast<const float4*>(Wt + ((size_t)i * O_REAL + oc) * 64);
        const float4* Bp = reinterpret_cast<const float4*>(Bt + ((size_t)i * O_REAL + oc) * 8);
        float wn[8];
        *reinterpret_cast<float4*>(&wn[0]) = *reinterpret_cast<const float4*>(&swin[i * 8]);
        *reinterpret_cast<float4*>(&wn[4]) = *reinterpret_cast<const float4*>(&swin[i * 8 + 4]);
        float4 bv0 = Bp[0], bv1 = Bp[1];
        float bb[8] = {bv0.x, bv0.y, bv0.z, bv0.w, bv1.x, bv1.y, bv1.z, bv1.w};
#pragma unroll
        for (int d = 0; d < 8; d++) {
            float4 w0 = Wp[d * 2], w1 = Wp[d * 2 + 1];
            float acc = bb[d];
            acc = fmaf(w0.x, wn[0], acc); acc = fmaf(w0.y, wn[1], acc);
            acc = fmaf(w0.z, wn[2], acc); acc = fmaf(w0.w, wn[3], acc);
            acc = fmaf(w1.x, wn[4], acc); acc = fmaf(w1.y, wn[5], acc);
            acc = fmaf(w1.z, wn[6], acc); acc = fmaf(w1.w, wn[7], acc);
            uj[jj][d] = (o < O_REAL) ? acc : 0.f;
        }
        bij[jj] = 0.f;
    }

    float mask = 0.f;
    if (LAYER == 1) { if (o == 0 || o >= O_REAL) mask = -1e9f; }

    int oo = tid >> 3, dd = tid & 7;
    float v_od = 0.f;

    for (int it = 0; it < 3; it++) {
        // coupling coefficients (softmax over o = lanes) + partial s
        float sp8[8] = {0, 0, 0, 0, 0, 0, 0, 0};
#pragma unroll
        for (int jj = 0; jj < 12; jj++) {
            float logit = bij[jj] + mask;
            float m = logit;
#pragma unroll
            for (int off = 16; off; off >>= 1)
                m = fmaxf(m, __shfl_xor_sync(0xffffffffu, m, off));
            float e = __expf(logit - m);
            float ssum = e;
#pragma unroll
            for (int off = 16; off; off >>= 1)
                ssum += __shfl_xor_sync(0xffffffffu, ssum, off);
            float c = e / ssum;
#pragma unroll
            for (int d = 0; d < 8; d++) sp8[d] = fmaf(c, uj[jj][d], sp8[d]);
        }
        *reinterpret_cast<float4*>(&sred[w * 256 + o * 8]) =
            make_float4(sp8[0], sp8[1], sp8[2], sp8[3]);
        *reinterpret_cast<float4*>(&sred[w * 256 + o * 8 + 4]) =
            make_float4(sp8[4], sp8[5], sp8[6], sp8[7]);
        __syncthreads();

        // reduce across warps, squash
        float s_od = 0.f;
#pragma unroll
        for (int w2 = 0; w2 < 8; w2++) s_od += sred[w2 * 256 + tid];
        float sq = s_od * s_od;
        sq += __shfl_xor_sync(0xffffffffu, sq, 1);
        sq += __shfl_xor_sync(0xffffffffu, sq, 2);
        sq += __shfl_xor_sync(0xffffffffu, sq, 4);
        v_od = s_od * (sq / (1.f + sq) * rsqrtf(sq + 1e-6f));
        sv[tid] = v_od;
        __syncthreads();

        // agreement update
        if (it < 2) {
            float vv[8];
            *reinterpret_cast<float4*>(&vv[0]) = *reinterpret_cast<const float4*>(&sv[o * 8]);
            *reinterpret_cast<float4*>(&vv[4]) = *reinterpret_cast<const float4*>(&sv[o * 8 + 4]);
#pragma unroll
            for (int jj = 0; jj < 12; jj++) {
                float acc = 0.f;
#pragma unroll
                for (int d = 0; d < 8; d++) acc = fmaf(uj[jj][d], vv[d], acc);
                bij[jj] += acc;
            }
        }
    }

    if (LAYER == 0) {
        // layernorm over 256 -> g_emb2
        float a = v_od, b2 = v_od * v_od;
        blockReduceSum2(a, b2);
        float mu = a * (1.f / 256.f);
        float var = b2 * (1.f / 256.f) - mu * mu;
        g_emb2[(size_t)p * 256 + tid] = (v_od - mu) * rsqrtf(var + 1e-3f);
    } else {
        // layernorm over 248 valid -> lengths -> layernorm over 31 -> out
        bool valid = (oo < O_REAL);
        float x = valid ? v_od : 0.f;
        float a = x, b2 = x * x;
        blockReduceSum2(a, b2);
        const float inv = 1.f / (float)(O_REAL * 8);
        float mu = a * inv;
        float var = b2 * inv - mu * mu;
        float vn = valid ? (x - mu) * rsqrtf(var + 1e-3f) : 0.f;
        float sq = vn * vn;
        sq += __shfl_xor_sync(0xffffffffu, sq, 1);
        sq += __shfl_xor_sync(0xffffffffu, sq, 2);
        sq += __shfl_xor_sync(0xffffffffu, sq, 4);
        if (dd == 0) slen[oo] = sqrtf(sq + 1e-6f);
        __syncthreads();
        if (tid < 32) {
            float l = (tid < O_REAL) ? slen[tid] : 0.f;
            float sa = l, sb = l * l;
#pragma unroll
            for (int off = 16; off; off >>= 1) {
                sa += __shfl_xor_sync(0xffffffffu, sa, off);
                sb += __shfl_xor_sync(0xffffffffu, sb, off);
            }
            float mu2 = sa / 31.f;
            float var2 = sb / 31.f - mu2 * mu2;
            if (tid < 31)
                out_final[(size_t)p * 31 + tid] = (l - mu2) * rsqrtf(var2 + 1e-3f);
        }
    }
}

// ---------------- launch ----------------
extern "C" void kernel_launch(void* const* d_in, const int* in_sizes, int n_in,
                              void* d_out, int out_size)
{
    (void)in_sizes; (void)n_in; (void)out_size;
    const float* inputs = (const float*)d_in[0];
    const float* c0w1 = (const float*)d_in[1];
    const float* c0b1 = (const float*)d_in[2];
    const float* c0w2 = (const float*)d_in[3];
    const float* c0b2 = (const float*)d_in[4];
    const float* c1w1 = (const float*)d_in[5];
    const float* c1b1 = (const float*)d_in[6];
    const float* c1w2 = (const float*)d_in[7];
    const float* c1b2 = (const float*)d_in[8];
    const float* pw   = (const float*)d_in[9];
    const float* pb   = (const float*)d_in[10];
    const float* ew1  = (const float*)d_in[11];
    const float* eb1  = (const float*)d_in[12];
    const float* ew2  = (const float*)d_in[13];
    const float* eb2  = (const float*)d_in[14];
    const float* W0   = (const float*)d_in[15];
    const float* B0   = (const float*)d_in[16];
    const float* W1   = (const float*)d_in[17];
    const float* B1   = (const float*)d_in[18];
    const int*   lens = (const int*)d_in[19];
    float* out = (float*)d_out;

    k_conv0<<<81920, 256>>>(inputs, c0w1, c0b1, c0w2, c0b2, lens);
    k_conv1<<<4096, 256>>>(c1w1, c1b1, c1w2, c1b2, lens);
    k_proj<<<512, 256>>>(pw, pb);
    k_enc<<<4096, 256>>>(ew1, eb1, ew2, eb2, lens);
    k_route<0><<<4096, 256>>>(W0, B0, nullptr);
    k_route<1><<<4096, 256>>>(W1, B1, out);
}

// round 3
// speedup vs baseline: 1.5441x; 1.5441x over previous
#include <cuda_runtime.h>
#include <cuda_bf16.h>
#include <cstdint>

// ---------------- scratch (device globals; no runtime allocation) ----------------
__device__ float g_x1[(size_t)8 * 1024 * 40 * 64];   // conv0 out [B,1024,40,64]
__device__ float g_x2[(size_t)8 * 512 * 20 * 64];    // conv1 out [B,512,20,64]
__device__ float g_p [(size_t)4096 * 32];            // proj out  [B*S,32]
__device__ float g_emb [(size_t)4096 * 256];         // primary caps [B*S,32,8]
__device__ float g_emb2[(size_t)4096 * 256];         // conv caps    [B*S,32,8]
__device__ float g_u[(size_t)4096 * 96 * 32 * 8];    // u_hat scratch (403MB), reused per layer
__device__ unsigned long long g_wp1[9 * 32 * 64];    // conv1 w1 packed (ic pairs)
__device__ unsigned long long g_wp2[9 * 32 * 64];    // conv1 w2 packed
__device__ unsigned long long g_pwp[640 * 32];       // proj w packed (k pairs)

// ---------------- helpers ----------------
__device__ __forceinline__ unsigned long long pack2(float x, float y) {
    unsigned long long r;
    asm("mov.b64 %0, {%1, %2};" : "=l"(r) : "f"(x), "f"(y));
    return r;
}
__device__ __forceinline__ void fma2(unsigned long long& c, unsigned long long a, unsigned long long b) {
    asm("fma.rn.f32x2 %0, %1, %2, %0;" : "+l"(c) : "l"(a), "l"(b));
}
__device__ __forceinline__ float2 unpack2(unsigned long long v) {
    float lo, hi;
    asm("mov.b64 {%0, %1}, %2;" : "=f"(lo), "=f"(hi) : "l"(v));
    return make_float2(lo, hi);
}

__device__ __forceinline__ void blockReduceSum2(float& a, float& b) {
    __shared__ float red[16];
    int lane = threadIdx.x & 31, w = threadIdx.x >> 5;
#pragma unroll
    for (int o = 16; o; o >>= 1) {
        a += __shfl_xor_sync(0xffffffffu, a, o);
        b += __shfl_xor_sync(0xffffffffu, b, o);
    }
    if (lane == 0) { red[w] = a; red[8 + w] = b; }
    __syncthreads();
    a = red[0] + red[1] + red[2] + red[3] + red[4] + red[5] + red[6] + red[7];
    b = red[8] + red[9] + red[10] + red[11] + red[12] + red[13] + red[14] + red[15];
    __syncthreads();
}

// ---------------- K0: weight pre-packing ----------------
__global__ void __launch_bounds__(256) k_prep(const float* __restrict__ w1,
                                              const float* __restrict__ w2,
                                              const float* __restrict__ pw)
{
    int idx = blockIdx.x * 256 + threadIdx.x;
    if (idx < 9 * 32 * 64) {
        int oc = idx & 63, r = idx >> 6;          // r = khkw*32 + ic2
        int khkw = r >> 5, ic2 = r & 31;
        int base = (khkw * 64 + ic2 * 2) * 64 + oc;
        g_wp1[idx] = pack2(w1[base], w1[base + 64]);
        g_wp2[idx] = pack2(w2[base], w2[base + 64]);
    }
    int pidx = idx - 9 * 32 * 64;
    if (pidx >= 0 && pidx < 640 * 32) {
        int col = pidx & 31, q = pidx >> 5;
        g_pwp[pidx] = pack2(pw[(2 * q) * 32 + col], pw[(2 * q + 1) * 32 + col]);
    }
}

// ---------------- K1: conv0 maxout + time mask ----------------
__global__ void __launch_bounds__(256) k_conv0(
    const float* __restrict__ in,
    const float* __restrict__ w1, const float* __restrict__ b1,
    const float* __restrict__ w2, const float* __restrict__ b2,
    const int* __restrict__ lens)
{
    __shared__ float sw1[576], sw2[576], sb[128];
    int tid = threadIdx.x;
    for (int i = tid; i < 576; i += 256) { sw1[i] = w1[i]; sw2[i] = w2[i]; }
    if (tid < 64) { sb[tid] = b1[tid]; sb[64 + tid] = b2[tid]; }
    __syncthreads();

    int idx = blockIdx.x * 256 + tid;
    int c = idx & 63;
    int t = idx >> 6;
    int ow = t % 40; t /= 40;
    int oh = t & 1023;
    int b  = t >> 10;

    int vl = (lens[b] + 1) >> 1;
    float out = 0.f;
    if (oh < vl) {
        float a1 = sb[c], a2 = sb[64 + c];
#pragma unroll
        for (int kh = 0; kh < 3; kh++) {
            int h = 2 * oh + kh;
            if (h < 2048) {
                const float* ir = in + ((size_t)b * 2048 + h) * 80;
#pragma unroll
                for (int kw = 0; kw < 3; kw++) {
                    int w = 2 * ow + kw;
                    if (w < 80) {
                        float v = ir[w];
                        int wi = (kh * 3 + kw) * 64 + c;
                        a1 = fmaf(v, sw1[wi], a1);
                        a2 = fmaf(v, sw2[wi], a2);
                    }
                }
            }
        }
        out = fmaxf(a1, a2);
    }
    g_x1[idx] = out;
}

// ---------------- K2: conv1 maxout (packed weights from g_wp1/g_wp2) ----------------
__global__ void __launch_bounds__(256) k_conv1(
    const float* __restrict__ b1, const float* __restrict__ b2,
    const int* __restrict__ lens)
{
    __shared__ float sin_[3 * 40 * 64];  // 30KB
    int tid = threadIdx.x;
    int b  = blockIdx.x >> 9;
    int oh = blockIdx.x & 511;

    for (int i = tid; i < 7680; i += 256) {
        int r = i / 2560, rem = i - r * 2560;
        int h = 2 * oh + r;
        sin_[i] = (h < 1024) ? g_x1[((size_t)b * 1024 + h) * 2560 + rem] : 0.f;
    }
    __syncthreads();

    int oc = tid & 63, wq = tid >> 6;
    unsigned long long acc1[5], acc2[5];
#pragma unroll
    for (int q = 0; q < 5; q++) {
        acc1[q] = pack2(b1[oc], 0.f);
        acc2[q] = pack2(b2[oc], 0.f);
    }

#pragma unroll
    for (int kh = 0; kh < 3; kh++) {
#pragma unroll
        for (int kw = 0; kw < 3; kw++) {
            int khkw = kh * 3 + kw;
            const unsigned long long* wr1 = g_wp1 + (size_t)khkw * 2048 + oc;
            const unsigned long long* wr2 = g_wp2 + (size_t)khkw * 2048 + oc;
            int off[5];
#pragma unroll
            for (int q = 0; q < 5; q++) {
                int w_in = 2 * (wq * 5 + q) + kw;
                off[q] = (w_in < 40) ? (kh * 40 + w_in) * 64 : -1;
            }
#pragma unroll 4
            for (int ic2 = 0; ic2 < 32; ic2++) {
                unsigned long long wp1 = wr1[ic2 * 64];
                unsigned long long wp2 = wr2[ic2 * 64];
#pragma unroll
                for (int q = 0; q < 5; q++) {
                    if (off[q] >= 0) {
                        unsigned long long vv =
                            *reinterpret_cast<const unsigned long long*>(&sin_[off[q] + ic2 * 2]);
                        fma2(acc1[q], vv, wp1);
                        fma2(acc2[q], vv, wp2);
                    }
                }
            }
        }
    }

    int vl = (lens[b] + 3) >> 2;
    float mask = (oh < vl) ? 1.f : 0.f;
#pragma unroll
    for (int q = 0; q < 5; q++) {
        float2 f1 = unpack2(acc1[q]);
        float2 f2 = unpack2(acc2[q]);
        int ow = wq * 5 + q;
        g_x2[(((size_t)b * 512 + oh) * 20 + ow) * 64 + oc] =
            fmaxf(f1.x + f1.y, f2.x + f2.y) * mask;
    }
}

// ---------------- K3a: projection (packed k-pairs) ----------------
__global__ void __launch_bounds__(256) k_proj(const float* __restrict__ pb)
{
    __shared__ float sx[8 * 1280];  // 40KB
    int tid = threadIdx.x;
    int b  = blockIdx.x >> 6;
    int s0 = (blockIdx.x & 63) << 3;
    const float* src = &g_x2[((size_t)b * 512 + s0) * 1280];
    for (int i = tid; i < 10240; i += 256) sx[i] = src[i];
    __syncthreads();

    int col = tid & 31, sl = tid >> 5;
    unsigned long long acc2 = pack2(pb[col], 0.f);
    const float* xr = &sx[sl * 1280];
    const unsigned long long* wp = g_pwp + col;
#pragma unroll 8
    for (int q = 0; q < 640; q++) {
        unsigned long long xv = *reinterpret_cast<const unsigned long long*>(&xr[2 * q]);
        fma2(acc2, xv, wp[q * 32]);
    }
    float2 f = unpack2(acc2);
    g_p[((size_t)b * 512 + s0 + sl) * 32 + col] = f.x + f.y;
}

// ---------------- K3b: encoder conv maxout + mask + squash + layernorm ----------------
__global__ void __launch_bounds__(256) k_enc(
    const float* __restrict__ ew1, const float* __restrict__ eb1,
    const float* __restrict__ ew2, const float* __restrict__ eb2,
    const int* __restrict__ lens)
{
    __shared__ float sp[3][32];
    __shared__ float sw[2][9][8];
    __shared__ float sbb[16];
    int tid = threadIdx.x;
    int p = blockIdx.x;
    int b = p >> 9, s = p & 511;

    if (tid < 96) {
        int j = tid >> 5, ii = tid & 31;
        int si = s + j - 1;
        sp[j][ii] = ((unsigned)si < 512u) ? g_p[((size_t)b * 512 + si) * 32 + ii] : 0.f;
    }
    if (tid < 72) { sw[0][tid / 8][tid & 7] = ew1[tid]; sw[1][tid / 8][tid & 7] = ew2[tid]; }
    if (tid < 16) sbb[tid] = (tid < 8) ? eb1[tid] : eb2[tid - 8];
    __syncthreads();

    int i = tid >> 3, d = tid & 7;
    float a1 = sbb[d], a2 = sbb[8 + d];
#pragma unroll
    for (int kh = 0; kh < 3; kh++)
#pragma unroll
        for (int kw = 0; kw < 3; kw++) {
            int ii = i + kw - 1;
            if ((unsigned)ii < 32u) {
                float v = sp[kh][ii];
                a1 = fmaf(v, sw[0][kh * 3 + kw][d], a1);
                a2 = fmaf(v, sw[1][kh * 3 + kw][d], a2);
            }
        }
    float e = fmaxf(a1, a2);
    int vl = (lens[b] + 3) >> 2;
    if (s >= vl) e = 0.f;

    float sq = e * e;
    sq += __shfl_xor_sync(0xffffffffu, sq, 1);
    sq += __shfl_xor_sync(0xffffffffu, sq, 2);
    sq += __shfl_xor_sync(0xffffffffu, sq, 4);
    float es = e * (sq / (1.f + sq) * rsqrtf(sq + 1e-6f));

    float a = es, b2 = es * es;
    blockReduceSum2(a, b2);
    float mu = a * (1.f / 256.f);
    float var = b2 * (1.f / 256.f) - mu * mu;
    g_emb[(size_t)p * 256 + tid] = (es - mu) * rsqrtf(var + 1e-3f);
}

// ---------------- K4a: u_hat GEMM (pass A) ----------------
// u[pos][i][o][d] = B[i,o,d] + sum_k W[i,o,d,k] * win[pos,i,k]
// block: (pos-tile of 64) x (i of 96). 256 threads: lane=o, grp=tid>>5 -> 8 positions each.
template <int LAYER>
__global__ void __launch_bounds__(256) k_uhat(const float* __restrict__ Wt,
                                              const float* __restrict__ Bt)
{
    constexpr int O_REAL = LAYER ? 31 : 32;
    __shared__ float sW[64 * 32];   // [dk][o] transposed
    __shared__ float sB[8 * 32];    // [d][o]
    __shared__ float sWin[64 * 8];  // [p_loc][k]
    const float* src = LAYER ? g_emb2 : g_emb;

    int tid = threadIdx.x;
    int i = blockIdx.y;
    int p0 = blockIdx.x * 64;

    if (O_REAL < 32) {
        for (int t = tid; t < 64 * 32; t += 256) sW[t] = 0.f;
        sB[tid] = 0.f;
        __syncthreads();
    }
    for (int t = tid; t < O_REAL * 64; t += 256) {
        int o = t >> 6, dk = t & 63;
        sW[dk * 32 + o] = Wt[((size_t)i * O_REAL + o) * 64 + dk];
    }
    for (int t = tid; t < O_REAL * 8; t += 256) {
        int o = t >> 3, d = t & 7;
        sB[d * 32 + o] = Bt[((size_t)i * O_REAL + o) * 8 + d];
    }
    {
        int j = i >> 5, ii = i & 31;
        for (int t = tid; t < 512; t += 256) {
            int pl = t >> 3, k = t & 7;
            int pos = p0 + pl;
            int b = pos >> 9, s = pos & 511;
            int sn = s + j - 1;
            sWin[t] = ((unsigned)sn < 512u)
                    ? src[(((size_t)b * 512 + sn) * 32 + ii) * 8 + k] : 0.f;
        }
    }
    __syncthreads();

    int o = tid & 31, grp = tid >> 5;
    float Wr[64];
#pragma unroll
    for (int dk = 0; dk < 64; dk++) Wr[dk] = sW[dk * 32 + o];
    float Br[8];
#pragma unroll
    for (int d = 0; d < 8; d++) Br[d] = sB[d * 32 + o];

#pragma unroll
    for (int ps = 0; ps < 8; ps++) {
        int pl = grp * 8 + ps;
        float wk[8];
        *reinterpret_cast<float4*>(&wk[0]) = *reinterpret_cast<const float4*>(&sWin[pl * 8]);
        *reinterpret_cast<float4*>(&wk[4]) = *reinterpret_cast<const float4*>(&sWin[pl * 8 + 4]);
        float acc[8];
#pragma unroll
        for (int d = 0; d < 8; d++) {
            float a = Br[d];
#pragma unroll
            for (int k = 0; k < 8; k++) a = fmaf(Wr[d * 8 + k], wk[k], a);
            acc[d] = a;
        }
        size_t pos = (size_t)(p0 + pl);
        float* dst = g_u + ((pos * 96 + i) * 32 + o) * 8;
        *reinterpret_cast<float4*>(dst)     = make_float4(acc[0], acc[1], acc[2], acc[3]);
        *reinterpret_cast<float4*>(dst + 4) = make_float4(acc[4], acc[5], acc[6], acc[7]);
    }
}

// ---------------- K4b: dynamic routing (pass B) ----------------
template <int LAYER>
__global__ void __launch_bounds__(256, 1) k_route(float* __restrict__ out_final)
{
    constexpr int O_REAL = LAYER ? 31 : 32;
    __shared__ float sred[8 * 256];
    __shared__ float sv[256];
    __shared__ float slen[32];

    int tid = threadIdx.x;
    int p = blockIdx.x;
    int w = tid >> 5, o = tid & 31;

    float uj[12][8];
    float bij[12];
    const float4* up = reinterpret_cast<const float4*>(
        g_u + (((size_t)p * 96 + w * 12) * 32 + o) * 8);
#pragma unroll
    for (int jj = 0; jj < 12; jj++) {
        float4 a = up[jj * 64];
        float4 c = up[jj * 64 + 1];
        uj[jj][0] = a.x; uj[jj][1] = a.y; uj[jj][2] = a.z; uj[jj][3] = a.w;
        uj[jj][4] = c.x; uj[jj][5] = c.y; uj[jj][6] = c.z; uj[jj][7] = c.w;
        bij[jj] = 0.f;
    }

    float mask = 0.f;
    if (LAYER == 1) { if (o == 0 || o >= O_REAL) mask = -1e9f; }

    int oo = tid >> 3, dd = tid & 7;
    float v_od = 0.f;

    for (int it = 0; it < 3; it++) {
        float sp8[8] = {0, 0, 0, 0, 0, 0, 0, 0};
#pragma unroll
        for (int jj = 0; jj < 12; jj++) {
            float logit = bij[jj] + mask;
            float m = logit;
#pragma unroll
            for (int off = 16; off; off >>= 1)
                m = fmaxf(m, __shfl_xor_sync(0xffffffffu, m, off));
            float e = __expf(logit - m);
            float ssum = e;
#pragma unroll
            for (int off = 16; off; off >>= 1)
                ssum += __shfl_xor_sync(0xffffffffu, ssum, off);
            float c = e / ssum;
#pragma unroll
            for (int d = 0; d < 8; d++) sp8[d] = fmaf(c, uj[jj][d], sp8[d]);
        }
        *reinterpret_cast<float4*>(&sred[w * 256 + o * 8]) =
            make_float4(sp8[0], sp8[1], sp8[2], sp8[3]);
        *reinterpret_cast<float4*>(&sred[w * 256 + o * 8 + 4]) =
            make_float4(sp8[4], sp8[5], sp8[6], sp8[7]);
        __syncthreads();

        float s_od = 0.f;
#pragma unroll
        for (int w2 = 0; w2 < 8; w2++) s_od += sred[w2 * 256 + tid];
        float sq = s_od * s_od;
        sq += __shfl_xor_sync(0xffffffffu, sq, 1);
        sq += __shfl_xor_sync(0xffffffffu, sq, 2);
        sq += __shfl_xor_sync(0xffffffffu, sq, 4);
        v_od = s_od * (sq / (1.f + sq) * rsqrtf(sq + 1e-6f));
        sv[tid] = v_od;
        __syncthreads();

        if (it < 2) {
            float vv[8];
            *reinterpret_cast<float4*>(&vv[0]) = *reinterpret_cast<const float4*>(&sv[o * 8]);
            *reinterpret_cast<float4*>(&vv[4]) = *reinterpret_cast<const float4*>(&sv[o * 8 + 4]);
#pragma unroll
            for (int jj = 0; jj < 12; jj++) {
                float acc = 0.f;
#pragma unroll
                for (int d = 0; d < 8; d++) acc = fmaf(uj[jj][d], vv[d], acc);
                bij[jj] += acc;
            }
        }
    }

    if (LAYER == 0) {
        float a = v_od, b2 = v_od * v_od;
        blockReduceSum2(a, b2);
        float mu = a * (1.f / 256.f);
        float var = b2 * (1.f / 256.f) - mu * mu;
        g_emb2[(size_t)p * 256 + tid] = (v_od - mu) * rsqrtf(var + 1e-3f);
    } else {
        bool valid = (oo < O_REAL);
        float x = valid ? v_od : 0.f;
        float a = x, b2 = x * x;
        blockReduceSum2(a, b2);
        const float inv = 1.f / (float)(O_REAL * 8);
        float mu = a * inv;
        float var = b2 * inv - mu * mu;
        float vn = valid ? (x - mu) * rsqrtf(var + 1e-3f) : 0.f;
        float sq = vn * vn;
        sq += __shfl_xor_sync(0xffffffffu, sq, 1);
        sq += __shfl_xor_sync(0xffffffffu, sq, 2);
        sq += __shfl_xor_sync(0xffffffffu, sq, 4);
        if (dd == 0) slen[oo] = sqrtf(sq + 1e-6f);
        __syncthreads();
        if (tid < 32) {
            float l = (tid < O_REAL) ? slen[tid] : 0.f;
            float sa = l, sb = l * l;
#pragma unroll
            for (int off = 16; off; off >>= 1) {
                sa += __shfl_xor_sync(0xffffffffu, sa, off);
                sb += __shfl_xor_sync(0xffffffffu, sb, off);
            }
            float mu2 = sa / 31.f;
            float var2 = sb / 31.f - mu2 * mu2;
            if (tid < 31)
                out_final[(size_t)p * 31 + tid] = (l - mu2) * rsqrtf(var2 + 1e-3f);
        }
    }
}

// ---------------- launch ----------------
extern "C" void kernel_launch(void* const* d_in, const int* in_sizes, int n_in,
                              void* d_out, int out_size)
{
    (void)in_sizes; (void)n_in; (void)out_size;
    const float* inputs = (const float*)d_in[0];
    const float* c0w1 = (const float*)d_in[1];
    const float* c0b1 = (const float*)d_in[2];
    const float* c0w2 = (const float*)d_in[3];
    const float* c0b2 = (const float*)d_in[4];
    const float* c1w1 = (const float*)d_in[5];
    const float* c1b1 = (const float*)d_in[6];
    const float* c1w2 = (const float*)d_in[7];
    const float* c1b2 = (const float*)d_in[8];
    const float* pw   = (const float*)d_in[9];
    const float* pb   = (const float*)d_in[10];
    const float* ew1  = (const float*)d_in[11];
    const float* eb1  = (const float*)d_in[12];
    const float* ew2  = (const float*)d_in[13];
    const float* eb2  = (const float*)d_in[14];
    const float* W0   = (const float*)d_in[15];
    const float* B0   = (const float*)d_in[16];
    const float* W1   = (const float*)d_in[17];
    const float* B1   = (const float*)d_in[18];
    const int*   lens = (const int*)d_in[19];
    float* out = (float*)d_out;

    k_prep<<<152, 256>>>(c1w1, c1w2, pw);
    k_conv0<<<81920, 256>>>(inputs, c0w1, c0b1, c0w2, c0b2, lens);
    k_conv1<<<4096, 256>>>(c1b1, c1b2, lens);
    k_proj<<<512, 256>>>(pb);
    k_enc<<<4096, 256>>>(ew1, eb1, ew2, eb2, lens);
    k_uhat<0><<<dim3(64, 96), 256>>>(W0, B0);
    k_route<0><<<4096, 256>>>(nullptr);
    k_uhat<1><<<dim3(64, 96), 256>>>(W1, B1);
    k_route<1><<<4096, 256>>>(out);
}

// round 4
// speedup vs baseline: 1.6540x; 1.0712x over previous
#include <cuda_runtime.h>
#include <cuda_bf16.h>
#include <cuda_fp16.h>
#include <cstdint>

// ---------------- scratch (device globals; no runtime allocation) ----------------
__device__ float g_x1[(size_t)8 * 1024 * 40 * 64];   // conv0 out [B,1024,40,64]
__device__ float g_x2[(size_t)8 * 512 * 20 * 64];    // conv1 out [B,512,20,64]
__device__ float g_p [(size_t)4096 * 32];            // proj out  [B*S,32]
__device__ float g_emb [(size_t)4096 * 256];         // primary caps [B*S,32,8]
__device__ float g_emb2[(size_t)4096 * 256];         // conv caps    [B*S,32,8]
__device__ uint4 g_u[(size_t)4096 * 96 * 32];        // u_hat fp16 (8 halves per entry), 201MB
__device__ unsigned long long g_wp1[9 * 32 * 64];    // conv1 w1 packed (ic pairs)
__device__ unsigned long long g_wp2[9 * 32 * 64];    // conv1 w2 packed
__device__ unsigned long long g_pwp[640 * 32];       // proj w packed (k pairs)

// ---------------- helpers ----------------
__device__ __forceinline__ unsigned long long pack2(float x, float y) {
    unsigned long long r;
    asm("mov.b64 %0, {%1, %2};" : "=l"(r) : "f"(x), "f"(y));
    return r;
}
__device__ __forceinline__ void fma2(unsigned long long& c, unsigned long long a, unsigned long long b) {
    asm("fma.rn.f32x2 %0, %1, %2, %0;" : "+l"(c) : "l"(a), "l"(b));
}
__device__ __forceinline__ float2 unpack2(unsigned long long v) {
    float lo, hi;
    asm("mov.b64 {%0, %1}, %2;" : "=f"(lo), "=f"(hi) : "l"(v));
    return make_float2(lo, hi);
}
__device__ __forceinline__ float2 h2f(unsigned u) {
    __half2 h = *reinterpret_cast<__half2*>(&u);
    return __half22float2(h);
}
__device__ __forceinline__ unsigned f2h(float a, float b) {
    __half2 h = __floats2half2_rn(a, b);
    return *reinterpret_cast<unsigned*>(&h);
}

__device__ __forceinline__ void blockReduceSum2(float& a, float& b) {
    __shared__ float red[16];
    int lane = threadIdx.x & 31, w = threadIdx.x >> 5;
#pragma unroll
    for (int o = 16; o; o >>= 1) {
        a += __shfl_xor_sync(0xffffffffu, a, o);
        b += __shfl_xor_sync(0xffffffffu, b, o);
    }
    if (lane == 0) { red[w] = a; red[8 + w] = b; }
    __syncthreads();
    a = red[0] + red[1] + red[2] + red[3] + red[4] + red[5] + red[6] + red[7];
    b = red[8] + red[9] + red[10] + red[11] + red[12] + red[13] + red[14] + red[15];
    __syncthreads();
}

// ---------------- K0: weight pre-packing ----------------
__global__ void __launch_bounds__(256) k_prep(const float* __restrict__ w1,
                                              const float* __restrict__ w2,
                                              const float* __restrict__ pw)
{
    int idx = blockIdx.x * 256 + threadIdx.x;
    if (idx < 9 * 32 * 64) {
        int oc = idx & 63, r = idx >> 6;
        int khkw = r >> 5, ic2 = r & 31;
        int base = (khkw * 64 + ic2 * 2) * 64 + oc;
        g_wp1[idx] = pack2(w1[base], w1[base + 64]);
        g_wp2[idx] = pack2(w2[base], w2[base + 64]);
    }
    int pidx = idx - 9 * 32 * 64;
    if (pidx >= 0 && pidx < 640 * 32) {
        int col = pidx & 31, q = pidx >> 5;
        g_pwp[pidx] = pack2(pw[(2 * q) * 32 + col], pw[(2 * q + 1) * 32 + col]);
    }
}

// ---------------- K1: conv0 maxout + time mask ----------------
// One block per (b, oh) output row: 40 ow x 64 ch. 10 outputs/thread.
__global__ void __launch_bounds__(256) k_conv0(
    const float* __restrict__ in,
    const float* __restrict__ w1, const float* __restrict__ b1,
    const float* __restrict__ w2, const float* __restrict__ b2,
    const int* __restrict__ lens)
{
    __shared__ float sw1[576], sw2[576], sb[128];
    __shared__ float sin_[3][80];
    int tid = threadIdx.x;
    int b  = blockIdx.x >> 10;
    int oh = blockIdx.x & 1023;

    for (int i = tid; i < 576; i += 256) { sw1[i] = w1[i]; sw2[i] = w2[i]; }
    if (tid < 64) { sb[tid] = b1[tid]; sb[64 + tid] = b2[tid]; }
    if (tid < 240) {
        int r = tid / 80, w = tid - r * 80;
        int h = 2 * oh + r;
        sin_[r][w] = (h < 2048) ? in[((size_t)b * 2048 + h) * 80 + w] : 0.f;
    }
    __syncthreads();

    int c = tid & 63, owg = tid >> 6;
    int vl = (lens[b] + 1) >> 1;
    float* dst = &g_x1[(((size_t)b * 1024 + oh) * 40) * 64 + c];

    if (oh < vl) {
#pragma unroll
        for (int q = 0; q < 10; q++) {
            int ow = owg * 10 + q;
            float a1 = sb[c], a2 = sb[64 + c];
#pragma unroll
            for (int kh = 0; kh < 3; kh++)
#pragma unroll
                for (int kw = 0; kw < 3; kw++) {
                    int w_in = 2 * ow + kw;
                    if (w_in < 80) {
                        float v = sin_[kh][w_in];
                        int wi = (kh * 3 + kw) * 64 + c;
                        a1 = fmaf(v, sw1[wi], a1);
                        a2 = fmaf(v, sw2[wi], a2);
                    }
                }
            dst[(size_t)ow * 64] = fmaxf(a1, a2);
        }
    } else {
#pragma unroll
        for (int q = 0; q < 10; q++) dst[(size_t)(owg * 10 + q) * 64] = 0.f;
    }
}

// ---------------- K2: conv1 maxout, 2 output rows per block (dynamic smem) ----------------
__global__ void __launch_bounds__(512) k_conv1(
    const float* __restrict__ b1, const float* __restrict__ b2,
    const int* __restrict__ lens)
{
    extern __shared__ float sin_[];  // 5 rows * 40 * 64 = 12800 floats (51.2KB)
    int tid = threadIdx.x;
    int b   = blockIdx.x >> 8;
    int ohp = blockIdx.x & 255;      // oh pair index; oh0 = 2*ohp

    for (int i = tid; i < 12800; i += 512) {
        int r = i / 2560, rem = i - r * 2560;
        int h = 4 * ohp + r;
        sin_[i] = (h < 1024) ? g_x1[((size_t)b * 1024 + h) * 2560 + rem] : 0.f;
    }
    __syncthreads();

    int oc = tid & 63;
    int g  = tid >> 6;          // 0..7
    int wq = g & 3;             // 0..3 -> 5 ow each
    int r2 = g >> 2;            // 0..1 row within pair
    int oh = 2 * ohp + r2;

    unsigned long long acc1[5], acc2[5];
#pragma unroll
    for (int q = 0; q < 5; q++) {
        acc1[q] = pack2(b1[oc], 0.f);
        acc2[q] = pack2(b2[oc], 0.f);
    }

#pragma unroll
    for (int kh = 0; kh < 3; kh++) {
#pragma unroll
        for (int kw = 0; kw < 3; kw++) {
            int khkw = kh * 3 + kw;
            const unsigned long long* wr1 = g_wp1 + (size_t)khkw * 2048 + oc;
            const unsigned long long* wr2 = g_wp2 + (size_t)khkw * 2048 + oc;
            int off[5];
#pragma unroll
            for (int q = 0; q < 5; q++) {
                int w_in = 2 * (wq * 5 + q) + kw;
                off[q] = (w_in < 40) ? ((2 * r2 + kh) * 40 + w_in) * 64 : -1;
            }
#pragma unroll 4
            for (int ic2 = 0; ic2 < 32; ic2++) {
                unsigned long long wp1 = wr1[ic2 * 64];
                unsigned long long wp2 = wr2[ic2 * 64];
#pragma unroll
                for (int q = 0; q < 5; q++) {
                    if (off[q] >= 0) {
                        unsigned long long vv =
                            *reinterpret_cast<const unsigned long long*>(&sin_[off[q] + ic2 * 2]);
                        fma2(acc1[q], vv, wp1);
                        fma2(acc2[q], vv, wp2);
                    }
                }
            }
        }
    }

    int vl = (lens[b] + 3) >> 2;
    float mask = (oh < vl) ? 1.f : 0.f;
#pragma unroll
    for (int q = 0; q < 5; q++) {
        float2 f1 = unpack2(acc1[q]);
        float2 f2 = unpack2(acc2[q]);
        int ow = wq * 5 + q;
        g_x2[(((size_t)b * 512 + oh) * 20 + ow) * 64 + oc] =
            fmaxf(f1.x + f1.y, f2.x + f2.y) * mask;
    }
}

// ---------------- K3a: projection (packed k-pairs) ----------------
__global__ void __launch_bounds__(256) k_proj(const float* __restrict__ pb)
{
    __shared__ float sx[8 * 1280];  // 40KB
    int tid = threadIdx.x;
    int b  = blockIdx.x >> 6;
    int s0 = (blockIdx.x & 63) << 3;
    const float* src = &g_x2[((size_t)b * 512 + s0) * 1280];
    for (int i = tid; i < 10240; i += 256) sx[i] = src[i];
    __syncthreads();

    int col = tid & 31, sl = tid >> 5;
    unsigned long long acc2 = pack2(pb[col], 0.f);
    const float* xr = &sx[sl * 1280];
    const unsigned long long* wp = g_pwp + col;
#pragma unroll 8
    for (int q = 0; q < 640; q++) {
        unsigned long long xv = *reinterpret_cast<const unsigned long long*>(&xr[2 * q]);
        fma2(acc2, xv, wp[q * 32]);
    }
    float2 f = unpack2(acc2);
    g_p[((size_t)b * 512 + s0 + sl) * 32 + col] = f.x + f.y;
}

// ---------------- K3b: encoder conv maxout + mask + squash + layernorm ----------------
__global__ void __launch_bounds__(256) k_enc(
    const float* __restrict__ ew1, const float* __restrict__ eb1,
    const float* __restrict__ ew2, const float* __restrict__ eb2,
    const int* __restrict__ lens)
{
    __shared__ float sp[3][32];
    __shared__ float sw[2][9][8];
    __shared__ float sbb[16];
    int tid = threadIdx.x;
    int p = blockIdx.x;
    int b = p >> 9, s = p & 511;

    if (tid < 96) {
        int j = tid >> 5, ii = tid & 31;
        int si = s + j - 1;
        sp[j][ii] = ((unsigned)si < 512u) ? g_p[((size_t)b * 512 + si) * 32 + ii] : 0.f;
    }
    if (tid < 72) { sw[0][tid / 8][tid & 7] = ew1[tid]; sw[1][tid / 8][tid & 7] = ew2[tid]; }
    if (tid < 16) sbb[tid] = (tid < 8) ? eb1[tid] : eb2[tid - 8];
    __syncthreads();

    int i = tid >> 3, d = tid & 7;
    float a1 = sbb[d], a2 = sbb[8 + d];
#pragma unroll
    for (int kh = 0; kh < 3; kh++)
#pragma unroll
        for (int kw = 0; kw < 3; kw++) {
            int ii = i + kw - 1;
            if ((unsigned)ii < 32u) {
                float v = sp[kh][ii];
                a1 = fmaf(v, sw[0][kh * 3 + kw][d], a1);
                a2 = fmaf(v, sw[1][kh * 3 + kw][d], a2);
            }
        }
    float e = fmaxf(a1, a2);
    int vl = (lens[b] + 3) >> 2;
    if (s >= vl) e = 0.f;

    float sq = e * e;
    sq += __shfl_xor_sync(0xffffffffu, sq, 1);
    sq += __shfl_xor_sync(0xffffffffu, sq, 2);
    sq += __shfl_xor_sync(0xffffffffu, sq, 4);
    float es = e * (sq / (1.f + sq) * rsqrtf(sq + 1e-6f));

    float a = es, b2 = es * es;
    blockReduceSum2(a, b2);
    float mu = a * (1.f / 256.f);
    float var = b2 * (1.f / 256.f) - mu * mu;
    g_emb[(size_t)p * 256 + tid] = (es - mu) * rsqrtf(var + 1e-3f);
}

// ---------------- K4a: u_hat GEMM -> fp16 ----------------
template <int LAYER>
__global__ void __launch_bounds__(256) k_uhat(const float* __restrict__ Wt,
                                              const float* __restrict__ Bt)
{
    constexpr int O_REAL = LAYER ? 31 : 32;
    __shared__ float sW[64 * 32];   // [dk][o]
    __shared__ float sB[8 * 32];    // [d][o]
    __shared__ float sWin[64 * 8];  // [p_loc][k]
    const float* src = LAYER ? g_emb2 : g_emb;

    int tid = threadIdx.x;
    int i = blockIdx.y;
    int p0 = blockIdx.x * 64;

    if (O_REAL < 32) {
        for (int t = tid; t < 64 * 32; t += 256) sW[t] = 0.f;
        sB[tid] = 0.f;
        __syncthreads();
    }
    for (int t = tid; t < O_REAL * 64; t += 256) {
        int o = t >> 6, dk = t & 63;
        sW[dk * 32 + o] = Wt[((size_t)i * O_REAL + o) * 64 + dk];
    }
    for (int t = tid; t < O_REAL * 8; t += 256) {
        int o = t >> 3, d = t & 7;
        sB[d * 32 + o] = Bt[((size_t)i * O_REAL + o) * 8 + d];
    }
    {
        int j = i >> 5, ii = i & 31;
        for (int t = tid; t < 512; t += 256) {
            int pl = t >> 3, k = t & 7;
            int pos = p0 + pl;
            int b = pos >> 9, s = pos & 511;
            int sn = s + j - 1;
            sWin[t] = ((unsigned)sn < 512u)
                    ? src[(((size_t)b * 512 + sn) * 32 + ii) * 8 + k] : 0.f;
        }
    }
    __syncthreads();

    int o = tid & 31, grp = tid >> 5;
    float Wr[64];
#pragma unroll
    for (int dk = 0; dk < 64; dk++) Wr[dk] = sW[dk * 32 + o];
    float Br[8];
#pragma unroll
    for (int d = 0; d < 8; d++) Br[d] = sB[d * 32 + o];

#pragma unroll
    for (int ps = 0; ps < 8; ps++) {
        int pl = grp * 8 + ps;
        float wk[8];
        *reinterpret_cast<float4*>(&wk[0]) = *reinterpret_cast<const float4*>(&sWin[pl * 8]);
        *reinterpret_cast<float4*>(&wk[4]) = *reinterpret_cast<const float4*>(&sWin[pl * 8 + 4]);
        float acc[8];
#pragma unroll
        for (int d = 0; d < 8; d++) {
            float a = Br[d];
#pragma unroll
            for (int k = 0; k < 8; k++) a = fmaf(Wr[d * 8 + k], wk[k], a);
            acc[d] = a;
        }
        size_t pos = (size_t)(p0 + pl);
        uint4 uv;
        uv.x = f2h(acc[0], acc[1]);
        uv.y = f2h(acc[2], acc[3]);
        uv.z = f2h(acc[4], acc[5]);
        uv.w = f2h(acc[6], acc[7]);
        g_u[(pos * 96 + i) * 32 + o] = uv;
    }
}

// ---------------- K4b: dynamic routing (u fp16 in registers) ----------------
template <int LAYER>
__global__ void __launch_bounds__(256) k_route(float* __restrict__ out_final)
{
    constexpr int O_REAL = LAYER ? 31 : 32;
    __shared__ float sred[8 * 256];
    __shared__ float sv[256];
    __shared__ float slen[32];

    int tid = threadIdx.x;
    int p = blockIdx.x;
    int w = tid >> 5, o = tid & 31;

    unsigned uh[12][4];
    float bij[12];
    const uint4* up = &g_u[(((size_t)p * 96 + w * 12) * 32 + o)];
#pragma unroll
    for (int jj = 0; jj < 12; jj++) {
        uint4 uv = up[jj * 32];
        uh[jj][0] = uv.x; uh[jj][1] = uv.y; uh[jj][2] = uv.z; uh[jj][3] = uv.w;
        bij[jj] = 0.f;
    }

    float mask = 0.f;
    if (LAYER == 1) { if (o == 0 || o >= O_REAL) mask = -1e9f; }

    int oo = tid >> 3, dd = tid & 7;
    float v_od = 0.f;

    for (int it = 0; it < 3; it++) {
        float sp8[8] = {0, 0, 0, 0, 0, 0, 0, 0};
#pragma unroll
        for (int jj = 0; jj < 12; jj++) {
            float logit = bij[jj] + mask;
            float m = logit;
#pragma unroll
            for (int off = 16; off; off >>= 1)
                m = fmaxf(m, __shfl_xor_sync(0xffffffffu, m, off));
            float e = __expf(logit - m);
            float ssum = e;
#pragma unroll
            for (int off = 16; off; off >>= 1)
                ssum += __shfl_xor_sync(0xffffffffu, ssum, off);
            float c = e / ssum;
#pragma unroll
            for (int t = 0; t < 4; t++) {
                float2 f = h2f(uh[jj][t]);
                sp8[2 * t]     = fmaf(c, f.x, sp8[2 * t]);
                sp8[2 * t + 1] = fmaf(c, f.y, sp8[2 * t + 1]);
            }
        }
        *reinterpret_cast<float4*>(&sred[w * 256 + o * 8]) =
            make_float4(sp8[0], sp8[1], sp8[2], sp8[3]);
        *reinterpret_cast<float4*>(&sred[w * 256 + o * 8 + 4]) =
            make_float4(sp8[4], sp8[5], sp8[6], sp8[7]);
        __syncthreads();

        float s_od = 0.f;
#pragma unroll
        for (int w2 = 0; w2 < 8; w2++) s_od += sred[w2 * 256 + tid];
        float sq = s_od * s_od;
        sq += __shfl_xor_sync(0xffffffffu, sq, 1);
        sq += __shfl_xor_sync(0xffffffffu, sq, 2);
        sq += __shfl_xor_sync(0xffffffffu, sq, 4);
        v_od = s_od * (sq / (1.f + sq) * rsqrtf(sq + 1e-6f));
        sv[tid] = v_od;
        __syncthreads();

        if (it < 2) {
            float vv[8];
            *reinterpret_cast<float4*>(&vv[0]) = *reinterpret_cast<const float4*>(&sv[o * 8]);
            *reinterpret_cast<float4*>(&vv[4]) = *reinterpret_cast<const float4*>(&sv[o * 8 + 4]);
#pragma unroll
            for (int jj = 0; jj < 12; jj++) {
                float acc = 0.f;
#pragma unroll
                for (int t = 0; t < 4; t++) {
                    float2 f = h2f(uh[jj][t]);
                    acc = fmaf(f.x, vv[2 * t], acc);
                    acc = fmaf(f.y, vv[2 * t + 1], acc);
                }
                bij[jj] += acc;
            }
        }
    }

    if (LAYER == 0) {
        float a = v_od, b2 = v_od * v_od;
        blockReduceSum2(a, b2);
        float mu = a * (1.f / 256.f);
        float var = b2 * (1.f / 256.f) - mu * mu;
        g_emb2[(size_t)p * 256 + tid] = (v_od - mu) * rsqrtf(var + 1e-3f);
    } else {
        bool valid = (oo < O_REAL);
        float x = valid ? v_od : 0.f;
        float a = x, b2 = x * x;
        blockReduceSum2(a, b2);
        const float inv = 1.f / (float)(O_REAL * 8);
        float mu = a * inv;
        float var = b2 * inv - mu * mu;
        float vn = valid ? (x - mu) * rsqrtf(var + 1e-3f) : 0.f;
        float sq = vn * vn;
        sq += __shfl_xor_sync(0xffffffffu, sq, 1);
        sq += __shfl_xor_sync(0xffffffffu, sq, 2);
        sq += __shfl_xor_sync(0xffffffffu, sq, 4);
        if (dd == 0) slen[oo] = sqrtf(sq + 1e-6f);
        __syncthreads();
        if (tid < 32) {
            float l = (tid < O_REAL) ? slen[tid] : 0.f;
            float sa = l, sb = l * l;
#pragma unroll
            for (int off = 16; off; off >>= 1) {
                sa += __shfl_xor_sync(0xffffffffu, sa, off);
                sb += __shfl_xor_sync(0xffffffffu, sb, off);
            }
            float mu2 = sa / 31.f;
            float var2 = sb / 31.f - mu2 * mu2;
            if (tid < 31)
                out_final[(size_t)p * 31 + tid] = (l - mu2) * rsqrtf(var2 + 1e-3f);
        }
    }
}

// ---------------- launch ----------------
extern "C" void kernel_launch(void* const* d_in, const int* in_sizes, int n_in,
                              void* d_out, int out_size)
{
    (void)in_sizes; (void)n_in; (void)out_size;
    const float* inputs = (const float*)d_in[0];
    const float* c0w1 = (const float*)d_in[1];
    const float* c0b1 = (const float*)d_in[2];
    const float* c0w2 = (const float*)d_in[3];
    const float* c0b2 = (const float*)d_in[4];
    const float* c1w1 = (const float*)d_in[5];
    const float* c1b1 = (const float*)d_in[6];
    const float* c1w2 = (const float*)d_in[7];
    const float* c1b2 = (const float*)d_in[8];
    const float* pw   = (const float*)d_in[9];
    const float* pb   = (const float*)d_in[10];
    const float* ew1  = (const float*)d_in[11];
    const float* eb1  = (const float*)d_in[12];
    const float* ew2  = (const float*)d_in[13];
    const float* eb2  = (const float*)d_in[14];
    const float* W0   = (const float*)d_in[15];
    const float* B0   = (const float*)d_in[16];
    const float* W1   = (const float*)d_in[17];
    const float* B1   = (const float*)d_in[18];
    const int*   lens = (const int*)d_in[19];
    float* out = (float*)d_out;

    static bool attr_done = false;
    if (!attr_done) {
        cudaFuncSetAttribute(k_conv1, cudaFuncAttributeMaxDynamicSharedMemorySize, 52224);
        attr_done = true;
    }

    k_prep<<<152, 256>>>(c1w1, c1w2, pw);
    k_conv0<<<8192, 256>>>(inputs, c0w1, c0b1, c0w2, c0b2, lens);
    k_conv1<<<2048, 512, 52224>>>(c1b1, c1b2, lens);
    k_proj<<<512, 256>>>(pb);
    k_enc<<<4096, 256>>>(ew1, eb1, ew2, eb2, lens);
    k_uhat<0><<<dim3(64, 96), 256>>>(W0, B0);
    k_route<0><<<4096, 256>>>(nullptr);
    k_uhat<1><<<dim3(64, 96), 256>>>(W1, B1);
    k_route<1><<<4096, 256>>>(out);
}

// round 5
// speedup vs baseline: 2.4220x; 1.4644x over previous
#include <cuda_runtime.h>
#include <cuda_bf16.h>
#include <cuda_fp16.h>
#include <cstdint>

// ---------------- scratch (device globals; no runtime allocation) ----------------
__device__ float g_x1[(size_t)8 * 1024 * 40 * 64];   // conv0 out [B,1024,40,64]
__device__ float g_x2[(size_t)8 * 512 * 20 * 64];    // conv1 out [B,512,20,64]
__device__ float g_p [(size_t)4096 * 32];            // proj out  [B*S,32]
__device__ float g_emb [(size_t)4096 * 256];         // primary caps [B*S,32,8]
__device__ float g_emb2[(size_t)4096 * 256];         // conv caps    [B*S,32,8]
__device__ uint4 g_u[(size_t)1024 * 96 * 32];        // u_hat fp16 chunk buffer (50MB, L2-resident)
__device__ unsigned long long g_wp1[9 * 32 * 64];    // conv1 w1 packed (ic pairs)
__device__ unsigned long long g_wp2[9 * 32 * 64];    // conv1 w2 packed
__device__ unsigned long long g_pwp[640 * 32];       // proj w packed (k pairs)

#define CHUNK 1024
#define NCHUNK 4

// ---------------- helpers ----------------
__device__ __forceinline__ unsigned long long pack2(float x, float y) {
    unsigned long long r;
    asm("mov.b64 %0, {%1, %2};" : "=l"(r) : "f"(x), "f"(y));
    return r;
}
__device__ __forceinline__ void fma2(unsigned long long& c, unsigned long long a, unsigned long long b) {
    asm("fma.rn.f32x2 %0, %1, %2, %0;" : "+l"(c) : "l"(a), "l"(b));
}
__device__ __forceinline__ float2 unpack2(unsigned long long v) {
    float lo, hi;
    asm("mov.b64 {%0, %1}, %2;" : "=f"(lo), "=f"(hi) : "l"(v));
    return make_float2(lo, hi);
}
__device__ __forceinline__ float2 h2f(unsigned u) {
    __half2 h = *reinterpret_cast<__half2*>(&u);
    return __half22float2(h);
}
__device__ __forceinline__ unsigned f2h(float a, float b) {
    __half2 h = __floats2half2_rn(a, b);
    return *reinterpret_cast<unsigned*>(&h);
}

__device__ __forceinline__ void blockReduceSum2(float& a, float& b) {
    __shared__ float red[16];
    int lane = threadIdx.x & 31, w = threadIdx.x >> 5;
#pragma unroll
    for (int o = 16; o; o >>= 1) {
        a += __shfl_xor_sync(0xffffffffu, a, o);
        b += __shfl_xor_sync(0xffffffffu, b, o);
    }
    if (lane == 0) { red[w] = a; red[8 + w] = b; }
    __syncthreads();
    a = red[0] + red[1] + red[2] + red[3] + red[4] + red[5] + red[6] + red[7];
    b = red[8] + red[9] + red[10] + red[11] + red[12] + red[13] + red[14] + red[15];
    __syncthreads();
}

// ---------------- K0: weight pre-packing ----------------
__global__ void __launch_bounds__(256) k_prep(const float* __restrict__ w1,
                                              const float* __restrict__ w2,
                                              const float* __restrict__ pw)
{
    int idx = blockIdx.x * 256 + threadIdx.x;
    if (idx < 9 * 32 * 64) {
        int oc = idx & 63, r = idx >> 6;
        int khkw = r >> 5, ic2 = r & 31;
        int base = (khkw * 64 + ic2 * 2) * 64 + oc;
        g_wp1[idx] = pack2(w1[base], w1[base + 64]);
        g_wp2[idx] = pack2(w2[base], w2[base + 64]);
    }
    int pidx = idx - 9 * 32 * 64;
    if (pidx >= 0 && pidx < 640 * 32) {
        int col = pidx & 31, q = pidx >> 5;
        g_pwp[pidx] = pack2(pw[(2 * q) * 32 + col], pw[(2 * q + 1) * 32 + col]);
    }
}

// ---------------- K1: conv0 maxout + time mask (4 output rows per block) ----------------
__global__ void __launch_bounds__(256) k_conv0(
    const float* __restrict__ in,
    const float* __restrict__ w1, const float* __restrict__ b1,
    const float* __restrict__ w2, const float* __restrict__ b2,
    const int* __restrict__ lens)
{
    __shared__ float sw1[576], sw2[576], sb[128];
    __shared__ float sin_[9][80];
    int tid = threadIdx.x;
    int b   = blockIdx.x >> 8;
    int oh0 = (blockIdx.x & 255) << 2;

    for (int i = tid; i < 576; i += 256) { sw1[i] = w1[i]; sw2[i] = w2[i]; }
    if (tid < 64) { sb[tid] = b1[tid]; sb[64 + tid] = b2[tid]; }
    for (int i = tid; i < 720; i += 256) {
        int r = i / 80, w = i - r * 80;
        int h = 2 * oh0 + r;
        sin_[r][w] = (h < 2048) ? in[((size_t)b * 2048 + h) * 80 + w] : 0.f;
    }
    __syncthreads();

    int c = tid & 63, owg = tid >> 6;
    int vl = (lens[b] + 1) >> 1;

#pragma unroll
    for (int r = 0; r < 4; r++) {
        int oh = oh0 + r;
        float* dst = &g_x1[(((size_t)b * 1024 + oh) * 40) * 64 + c];
        if (oh < vl) {
#pragma unroll
            for (int q = 0; q < 10; q++) {
                int ow = owg * 10 + q;
                float a1 = sb[c], a2 = sb[64 + c];
#pragma unroll
                for (int kh = 0; kh < 3; kh++)
#pragma unroll
                    for (int kw = 0; kw < 3; kw++) {
                        int w_in = 2 * ow + kw;
                        if (w_in < 80) {
                            float v = sin_[2 * r + kh][w_in];
                            int wi = (kh * 3 + kw) * 64 + c;
                            a1 = fmaf(v, sw1[wi], a1);
                            a2 = fmaf(v, sw2[wi], a2);
                        }
                    }
                dst[(size_t)ow * 64] = fmaxf(a1, a2);
            }
        } else {
#pragma unroll
            for (int q = 0; q < 10; q++) dst[(size_t)(owg * 10 + q) * 64] = 0.f;
        }
    }
}

// ---------------- K2: conv1 maxout, 2 output rows per block (dynamic smem) ----------------
__global__ void __launch_bounds__(512) k_conv1(
    const float* __restrict__ b1, const float* __restrict__ b2,
    const int* __restrict__ lens)
{
    extern __shared__ float sin_[];  // 5 rows * 40 * 64 = 12800 floats (51.2KB)
    int tid = threadIdx.x;
    int b   = blockIdx.x >> 8;
    int ohp = blockIdx.x & 255;

    for (int i = tid; i < 12800; i += 512) {
        int r = i / 2560, rem = i - r * 2560;
        int h = 4 * ohp + r;
        sin_[i] = (h < 1024) ? g_x1[((size_t)b * 1024 + h) * 2560 + rem] : 0.f;
    }
    __syncthreads();

    int oc = tid & 63;
    int g  = tid >> 6;
    int wq = g & 3;
    int r2 = g >> 2;
    int oh = 2 * ohp + r2;

    unsigned long long acc1[5], acc2[5];
#pragma unroll
    for (int q = 0; q < 5; q++) {
        acc1[q] = pack2(b1[oc], 0.f);
        acc2[q] = pack2(b2[oc], 0.f);
    }

#pragma unroll
    for (int kh = 0; kh < 3; kh++) {
#pragma unroll
        for (int kw = 0; kw < 3; kw++) {
            int khkw = kh * 3 + kw;
            const unsigned long long* wr1 = g_wp1 + (size_t)khkw * 2048 + oc;
            const unsigned long long* wr2 = g_wp2 + (size_t)khkw * 2048 + oc;
            int off[5];
#pragma unroll
            for (int q = 0; q < 5; q++) {
                int w_in = 2 * (wq * 5 + q) + kw;
                off[q] = (w_in < 40) ? ((2 * r2 + kh) * 40 + w_in) * 64 : -1;
            }
#pragma unroll 8
            for (int ic2 = 0; ic2 < 32; ic2++) {
                unsigned long long wp1 = wr1[ic2 * 64];
                unsigned long long wp2 = wr2[ic2 * 64];
#pragma unroll
                for (int q = 0; q < 5; q++) {
                    if (off[q] >= 0) {
                        unsigned long long vv =
                            *reinterpret_cast<const unsigned long long*>(&sin_[off[q] + ic2 * 2]);
                        fma2(acc1[q], vv, wp1);
                        fma2(acc2[q], vv, wp2);
                    }
                }
            }
        }
    }

    int vl = (lens[b] + 3) >> 2;
    float mask = (oh < vl) ? 1.f : 0.f;
#pragma unroll
    for (int q = 0; q < 5; q++) {
        float2 f1 = unpack2(acc1[q]);
        float2 f2 = unpack2(acc2[q]);
        int ow = wq * 5 + q;
        g_x2[(((size_t)b * 512 + oh) * 20 + ow) * 64 + oc] =
            fmaxf(f1.x + f1.y, f2.x + f2.y) * mask;
    }
}

// ---------------- K3a: projection (packed k-pairs, 4 accumulator chains) ----------------
__global__ void __launch_bounds__(256) k_proj(const float* __restrict__ pb)
{
    __shared__ float sx[8 * 1280];  // 40KB
    int tid = threadIdx.x;
    int b  = blockIdx.x >> 6;
    int s0 = (blockIdx.x & 63) << 3;
    const float* src = &g_x2[((size_t)b * 512 + s0) * 1280];
    for (int i = tid; i < 10240; i += 256) sx[i] = src[i];
    __syncthreads();

    int col = tid & 31, sl = tid >> 5;
    unsigned long long acc[4];
    acc[0] = pack2(pb[col], 0.f);
    acc[1] = 0; acc[2] = 0; acc[3] = 0;
    const float* xr = &sx[sl * 1280];
    const unsigned long long* wp = g_pwp + col;
#pragma unroll 4
    for (int q = 0; q < 640; q += 4) {
#pragma unroll
        for (int j = 0; j < 4; j++) {
            unsigned long long xv =
                *reinterpret_cast<const unsigned long long*>(&xr[2 * (q + j)]);
            fma2(acc[j], xv, wp[(q + j) * 32]);
        }
    }
    float2 f0 = unpack2(acc[0]), f1 = unpack2(acc[1]);
    float2 f2 = unpack2(acc[2]), f3 = unpack2(acc[3]);
    g_p[((size_t)b * 512 + s0 + sl) * 32 + col] =
        (f0.x + f0.y) + (f1.x + f1.y) + (f2.x + f2.y) + (f3.x + f3.y);
}

// ---------------- K3b: encoder conv maxout + mask + squash + layernorm ----------------
__global__ void __launch_bounds__(256) k_enc(
    const float* __restrict__ ew1, const float* __restrict__ eb1,
    const float* __restrict__ ew2, const float* __restrict__ eb2,
    const int* __restrict__ lens)
{
    __shared__ float sp[3][32];
    __shared__ float sw[2][9][8];
    __shared__ float sbb[16];
    int tid = threadIdx.x;
    int p = blockIdx.x;
    int b = p >> 9, s = p & 511;

    if (tid < 96) {
        int j = tid >> 5, ii = tid & 31;
        int si = s + j - 1;
        sp[j][ii] = ((unsigned)si < 512u) ? g_p[((size_t)b * 512 + si) * 32 + ii] : 0.f;
    }
    if (tid < 72) { sw[0][tid / 8][tid & 7] = ew1[tid]; sw[1][tid / 8][tid & 7] = ew2[tid]; }
    if (tid < 16) sbb[tid] = (tid < 8) ? eb1[tid] : eb2[tid - 8];
    __syncthreads();

    int i = tid >> 3, d = tid & 7;
    float a1 = sbb[d], a2 = sbb[8 + d];
#pragma unroll
    for (int kh = 0; kh < 3; kh++)
#pragma unroll
        for (int kw = 0; kw < 3; kw++) {
            int ii = i + kw - 1;
            if ((unsigned)ii < 32u) {
                float v = sp[kh][ii];
                a1 = fmaf(v, sw[0][kh * 3 + kw][d], a1);
                a2 = fmaf(v, sw[1][kh * 3 + kw][d], a2);
            }
        }
    float e = fmaxf(a1, a2);
    int vl = (lens[b] + 3) >> 2;
    if (s >= vl) e = 0.f;

    float sq = e * e;
    sq += __shfl_xor_sync(0xffffffffu, sq, 1);
    sq += __shfl_xor_sync(0xffffffffu, sq, 2);
    sq += __shfl_xor_sync(0xffffffffu, sq, 4);
    float es = e * (sq / (1.f + sq) * rsqrtf(sq + 1e-6f));

    float a = es, b2 = es * es;
    blockReduceSum2(a, b2);
    float mu = a * (1.f / 256.f);
    float var = b2 * (1.f / 256.f) - mu * mu;
    g_emb[(size_t)p * 256 + tid] = (es - mu) * rsqrtf(var + 1e-3f);
}

// ---------------- K4a: u_hat GEMM -> fp16 (chunked; g_u indexed locally) ----------------
template <int LAYER>
__global__ void __launch_bounds__(256) k_uhat(const float* __restrict__ Wt,
                                              const float* __restrict__ Bt,
                                              int pos_base)
{
    constexpr int O_REAL = LAYER ? 31 : 32;
    __shared__ float sW[64 * 32];   // [dk][o]
    __shared__ float sB[8 * 32];    // [d][o]
    __shared__ float sWin[64 * 8];  // [p_loc][k]
    const float* src = LAYER ? g_emb2 : g_emb;

    int tid = threadIdx.x;
    int i = blockIdx.y;
    int p0 = blockIdx.x * 64;       // local within chunk

    if (O_REAL < 32) {
        for (int t = tid; t < 64 * 32; t += 256) sW[t] = 0.f;
        sB[tid] = 0.f;
        __syncthreads();
    }
    for (int t = tid; t < O_REAL * 64; t += 256) {
        int o = t >> 6, dk = t & 63;
        sW[dk * 32 + o] = Wt[((size_t)i * O_REAL + o) * 64 + dk];
    }
    for (int t = tid; t < O_REAL * 8; t += 256) {
        int o = t >> 3, d = t & 7;
        sB[d * 32 + o] = Bt[((size_t)i * O_REAL + o) * 8 + d];
    }
    {
        int j = i >> 5, ii = i & 31;
        for (int t = tid; t < 512; t += 256) {
            int pl = t >> 3, k = t & 7;
            int pos = pos_base + p0 + pl;
            int b = pos >> 9, s = pos & 511;
            int sn = s + j - 1;
            sWin[t] = ((unsigned)sn < 512u)
                    ? src[(((size_t)b * 512 + sn) * 32 + ii) * 8 + k] : 0.f;
        }
    }
    __syncthreads();

    int o = tid & 31, grp = tid >> 5;
    float Wr[64];
#pragma unroll
    for (int dk = 0; dk < 64; dk++) Wr[dk] = sW[dk * 32 + o];
    float Br[8];
#pragma unroll
    for (int d = 0; d < 8; d++) Br[d] = sB[d * 32 + o];

#pragma unroll
    for (int ps = 0; ps < 8; ps++) {
        int pl = grp * 8 + ps;
        float wk[8];
        *reinterpret_cast<float4*>(&wk[0]) = *reinterpret_cast<const float4*>(&sWin[pl * 8]);
        *reinterpret_cast<float4*>(&wk[4]) = *reinterpret_cast<const float4*>(&sWin[pl * 8 + 4]);
        float acc[8];
#pragma unroll
        for (int d = 0; d < 8; d++) {
            float a = Br[d];
#pragma unroll
            for (int k = 0; k < 8; k++) a = fmaf(Wr[d * 8 + k], wk[k], a);
            acc[d] = a;
        }
        size_t posl = (size_t)(p0 + pl);
        uint4 uv;
        uv.x = f2h(acc[0], acc[1]);
        uv.y = f2h(acc[2], acc[3]);
        uv.z = f2h(acc[4], acc[5]);
        uv.w = f2h(acc[6], acc[7]);
        g_u[(posl * 96 + i) * 32 + o] = uv;
    }
}

// ---------------- K4b: dynamic routing (u fp16 in registers; chunked) ----------------
template <int LAYER>
__global__ void __launch_bounds__(256) k_route(float* __restrict__ out_final,
                                               int pos_base)
{
    constexpr int O_REAL = LAYER ? 31 : 32;
    __shared__ float sred[8 * 256];
    __shared__ float sv[256];
    __shared__ float slen[32];

    int tid = threadIdx.x;
    int pl = blockIdx.x;            // local within chunk
    int p  = pos_base + pl;         // global position
    int w = tid >> 5, o = tid & 31;

    unsigned uh[12][4];
    float bij[12];
    const uint4* up = &g_u[(((size_t)pl * 96 + w * 12) * 32 + o)];
#pragma unroll
    for (int jj = 0; jj < 12; jj++) {
        uint4 uv = up[jj * 32];
        uh[jj][0] = uv.x; uh[jj][1] = uv.y; uh[jj][2] = uv.z; uh[jj][3] = uv.w;
        bij[jj] = 0.f;
    }

    float mask = 0.f;
    if (LAYER == 1) { if (o == 0 || o >= O_REAL) mask = -1e9f; }

    int oo = tid >> 3, dd = tid & 7;
    float v_od = 0.f;

    for (int it = 0; it < 3; it++) {
        float sp8[8] = {0, 0, 0, 0, 0, 0, 0, 0};
#pragma unroll
        for (int jj = 0; jj < 12; jj++) {
            // softmax over o (lanes) without max-subtraction: logits bounded (|b|<~3),
            // masked lanes exp(-1e9)=0 exactly.
            float e = __expf(bij[jj] + mask);
            float ssum = e;
#pragma unroll
            for (int off = 16; off; off >>= 1)
                ssum += __shfl_xor_sync(0xffffffffu, ssum, off);
            float c = __fdividef(e, ssum);
#pragma unroll
            for (int t = 0; t < 4; t++) {
                float2 f = h2f(uh[jj][t]);
                sp8[2 * t]     = fmaf(c, f.x, sp8[2 * t]);
                sp8[2 * t + 1] = fmaf(c, f.y, sp8[2 * t + 1]);
            }
        }
        *reinterpret_cast<float4*>(&sred[w * 256 + o * 8]) =
            make_float4(sp8[0], sp8[1], sp8[2], sp8[3]);
        *reinterpret_cast<float4*>(&sred[w * 256 + o * 8 + 4]) =
            make_float4(sp8[4], sp8[5], sp8[6], sp8[7]);
        __syncthreads();

        float s_od = 0.f;
#pragma unroll
        for (int w2 = 0; w2 < 8; w2++) s_od += sred[w2 * 256 + tid];
        float sq = s_od * s_od;
        sq += __shfl_xor_sync(0xffffffffu, sq, 1);
        sq += __shfl_xor_sync(0xffffffffu, sq, 2);
        sq += __shfl_xor_sync(0xffffffffu, sq, 4);
        v_od = s_od * (sq / (1.f + sq) * rsqrtf(sq + 1e-6f));
        sv[tid] = v_od;
        __syncthreads();

        if (it < 2) {
            float vv[8];
            *reinterpret_cast<float4*>(&vv[0]) = *reinterpret_cast<const float4*>(&sv[o * 8]);
            *reinterpret_cast<float4*>(&vv[4]) = *reinterpret_cast<const float4*>(&sv[o * 8 + 4]);
#pragma unroll
            for (int jj = 0; jj < 12; jj++) {
                float acc = 0.f;
#pragma unroll
                for (int t = 0; t < 4; t++) {
                    float2 f = h2f(uh[jj][t]);
                    acc = fmaf(f.x, vv[2 * t], acc);
                    acc = fmaf(f.y, vv[2 * t + 1], acc);
                }
                bij[jj] += acc;
            }
        }
    }

    if (LAYER == 0) {
        float a = v_od, b2 = v_od * v_od;
        blockReduceSum2(a, b2);
        float mu = a * (1.f / 256.f);
        float var = b2 * (1.f / 256.f) - mu * mu;
        g_emb2[(size_t)p * 256 + tid] = (v_od - mu) * rsqrtf(var + 1e-3f);
    } else {
        bool valid = (oo < O_REAL);
        float x = valid ? v_od : 0.f;
        float a = x, b2 = x * x;
        blockReduceSum2(a, b2);
        const float inv = 1.f / (float)(O_REAL * 8);
        float mu = a * inv;
        float var = b2 * inv - mu * mu;
        float vn = valid ? (x - mu) * rsqrtf(var + 1e-3f) : 0.f;
        float sq = vn * vn;
        sq += __shfl_xor_sync(0xffffffffu, sq, 1);
        sq += __shfl_xor_sync(0xffffffffu, sq, 2);
        sq += __shfl_xor_sync(0xffffffffu, sq, 4);
        if (dd == 0) slen[oo] = sqrtf(sq + 1e-6f);
        __syncthreads();
        if (tid < 32) {
            float l = (tid < O_REAL) ? slen[tid] : 0.f;
            float sa = l, sb = l * l;
#pragma unroll
            for (int off = 16; off; off >>= 1) {
                sa += __shfl_xor_sync(0xffffffffu, sa, off);
                sb += __shfl_xor_sync(0xffffffffu, sb, off);
            }
            float mu2 = sa / 31.f;
            float var2 = sb / 31.f - mu2 * mu2;
            if (tid < 31)
                out_final[(size_t)p * 31 + tid] = (l - mu2) * rsqrtf(var2 + 1e-3f);
        }
    }
}

// ---------------- launch ----------------
extern "C" void kernel_launch(void* const* d_in, const int* in_sizes, int n_in,
                              void* d_out, int out_size)
{
    (void)in_sizes; (void)n_in; (void)out_size;
    const float* inputs = (const float*)d_in[0];
    const float* c0w1 = (const float*)d_in[1];
    const float* c0b1 = (const float*)d_in[2];
    const float* c0w2 = (const float*)d_in[3];
    const float* c0b2 = (const float*)d_in[4];
    const float* c1w1 = (const float*)d_in[5];
    const float* c1b1 = (const float*)d_in[6];
    const float* c1w2 = (const float*)d_in[7];
    const float* c1b2 = (const float*)d_in[8];
    const float* pw   = (const float*)d_in[9];
    const float* pb   = (const float*)d_in[10];
    const float* ew1  = (const float*)d_in[11];
    const float* eb1  = (const float*)d_in[12];
    const float* ew2  = (const float*)d_in[13];
    const float* eb2  = (const float*)d_in[14];
    const float* W0   = (const float*)d_in[15];
    const float* B0   = (const float*)d_in[16];
    const float* W1   = (const float*)d_in[17];
    const float* B1   = (const float*)d_in[18];
    const int*   lens = (const int*)d_in[19];
    float* out = (float*)d_out;

    static bool attr_done = false;
    if (!attr_done) {
        cudaFuncSetAttribute(k_conv1, cudaFuncAttributeMaxDynamicSharedMemorySize, 52224);
        attr_done = true;
    }

    k_prep<<<152, 256>>>(c1w1, c1w2, pw);
    k_conv0<<<2048, 256>>>(inputs, c0w1, c0b1, c0w2, c0b2, lens);
    k_conv1<<<2048, 512, 52224>>>(c1b1, c1b2, lens);
    k_proj<<<512, 256>>>(pb);
    k_enc<<<4096, 256>>>(ew1, eb1, ew2, eb2, lens);

    // chunked routing pipeline: u buffer stays L2-resident
    for (int c = 0; c < NCHUNK; c++) {
        int base = c * CHUNK;
        k_uhat<0><<<dim3(CHUNK / 64, 96), 256>>>(W0, B0, base);
        k_route<0><<<CHUNK, 256>>>(nullptr, base);
        k_uhat<1><<<dim3(CHUNK / 64, 96), 256>>>(W1, B1, base);
        k_route<1><<<CHUNK, 256>>>(out, base);
    }
}

// round 6
// speedup vs baseline: 2.5444x; 1.0505x over previous
#include <cuda_runtime.h>
#include <cuda_bf16.h>
#include <cuda_fp16.h>
#include <cstdint>

// ---------------- scratch (device globals; no runtime allocation) ----------------
__device__ float g_x1[(size_t)8 * 1024 * 40 * 64];   // conv0 out [B,1024,40,64]
__device__ float g_x2[(size_t)8 * 512 * 20 * 64];    // conv1 out [B,512,20,64]
__device__ float g_p [(size_t)4096 * 32];            // proj out  [B*S,32]
__device__ float g_emb [(size_t)4096 * 256];         // primary caps [B*S,32,8]
__device__ float g_emb2[(size_t)4096 * 256];         // conv caps    [B*S,32,8]
__device__ uint4 g_ubuf[2][(size_t)512 * 96 * 32];   // u_hat fp16 double buffer (2x25MB, L2-resident)
__device__ unsigned long long g_wp1[9 * 32 * 64];    // conv1 w1 packed (ic pairs)
__device__ unsigned long long g_wp2[9 * 32 * 64];    // conv1 w2 packed
__device__ unsigned long long g_pwp[640 * 32];       // proj w packed (k pairs)

#define CHUNK 512
#define NCHUNK 8

// ---------------- helpers ----------------
__device__ __forceinline__ unsigned long long pack2(float x, float y) {
    unsigned long long r;
    asm("mov.b64 %0, {%1, %2};" : "=l"(r) : "f"(x), "f"(y));
    return r;
}
__device__ __forceinline__ void fma2(unsigned long long& c, unsigned long long a, unsigned long long b) {
    asm("fma.rn.f32x2 %0, %1, %2, %0;" : "+l"(c) : "l"(a), "l"(b));
}
__device__ __forceinline__ float2 unpack2(unsigned long long v) {
    float lo, hi;
    asm("mov.b64 {%0, %1}, %2;" : "=f"(lo), "=f"(hi) : "l"(v));
    return make_float2(lo, hi);
}
__device__ __forceinline__ float2 h2f(unsigned u) {
    __half2 h = *reinterpret_cast<__half2*>(&u);
    return __half22float2(h);
}
__device__ __forceinline__ unsigned f2h(float a, float b) {
    __half2 h = __floats2half2_rn(a, b);
    return *reinterpret_cast<unsigned*>(&h);
}

__device__ __forceinline__ void blockReduceSum2(float& a, float& b) {
    __shared__ float red[16];
    int lane = threadIdx.x & 31, w = threadIdx.x >> 5;
#pragma unroll
    for (int o = 16; o; o >>= 1) {
        a += __shfl_xor_sync(0xffffffffu, a, o);
        b += __shfl_xor_sync(0xffffffffu, b, o);
    }
    if (lane == 0) { red[w] = a; red[8 + w] = b; }
    __syncthreads();
    a = red[0] + red[1] + red[2] + red[3] + red[4] + red[5] + red[6] + red[7];
    b = red[8] + red[9] + red[10] + red[11] + red[12] + red[13] + red[14] + red[15];
    __syncthreads();
}

// ---------------- K0: weight pre-packing ----------------
__global__ void __launch_bounds__(256) k_prep(const float* __restrict__ w1,
                                              const float* __restrict__ w2,
                                              const float* __restrict__ pw)
{
    int idx = blockIdx.x * 256 + threadIdx.x;
    if (idx < 9 * 32 * 64) {
        int oc = idx & 63, r = idx >> 6;
        int khkw = r >> 5, ic2 = r & 31;
        int base = (khkw * 64 + ic2 * 2) * 64 + oc;
        g_wp1[idx] = pack2(w1[base], w1[base + 64]);
        g_wp2[idx] = pack2(w2[base], w2[base + 64]);
    }
    int pidx = idx - 9 * 32 * 64;
    if (pidx >= 0 && pidx < 640 * 32) {
        int col = pidx & 31, q = pidx >> 5;
        g_pwp[pidx] = pack2(pw[(2 * q) * 32 + col], pw[(2 * q + 1) * 32 + col]);
    }
}

// ---------------- K1: conv0 maxout + time mask (4 output rows per block) ----------------
__global__ void __launch_bounds__(256) k_conv0(
    const float* __restrict__ in,
    const float* __restrict__ w1, const float* __restrict__ b1,
    const float* __restrict__ w2, const float* __restrict__ b2,
    const int* __restrict__ lens)
{
    __shared__ float sw1[576], sw2[576], sb[128];
    __shared__ float sin_[9][80];
    int tid = threadIdx.x;
    int b   = blockIdx.x >> 8;
    int oh0 = (blockIdx.x & 255) << 2;

    for (int i = tid; i < 576; i += 256) { sw1[i] = w1[i]; sw2[i] = w2[i]; }
    if (tid < 64) { sb[tid] = b1[tid]; sb[64 + tid] = b2[tid]; }
    for (int i = tid; i < 720; i += 256) {
        int r = i / 80, w = i - r * 80;
        int h = 2 * oh0 + r;
        sin_[r][w] = (h < 2048) ? in[((size_t)b * 2048 + h) * 80 + w] : 0.f;
    }
    __syncthreads();

    int c = tid & 63, owg = tid >> 6;
    int vl = (lens[b] + 1) >> 1;

#pragma unroll
    for (int r = 0; r < 4; r++) {
        int oh = oh0 + r;
        float* dst = &g_x1[(((size_t)b * 1024 + oh) * 40) * 64 + c];
        if (oh < vl) {
#pragma unroll
            for (int q = 0; q < 10; q++) {
                int ow = owg * 10 + q;
                float a1 = sb[c], a2 = sb[64 + c];
#pragma unroll
                for (int kh = 0; kh < 3; kh++)
#pragma unroll
                    for (int kw = 0; kw < 3; kw++) {
                        int w_in = 2 * ow + kw;
                        if (w_in < 80) {
                            float v = sin_[2 * r + kh][w_in];
                            int wi = (kh * 3 + kw) * 64 + c;
                            a1 = fmaf(v, sw1[wi], a1);
                            a2 = fmaf(v, sw2[wi], a2);
                        }
                    }
                dst[(size_t)ow * 64] = fmaxf(a1, a2);
            }
        } else {
#pragma unroll
            for (int q = 0; q < 10; q++) dst[(size_t)(owg * 10 + q) * 64] = 0.f;
        }
    }
}

// ---------------- K2: conv1 maxout, 2 output rows per block (dynamic smem) ----------------
__global__ void __launch_bounds__(512) k_conv1(
    const float* __restrict__ b1, const float* __restrict__ b2,
    const int* __restrict__ lens)
{
    extern __shared__ float sin_[];  // 5 rows * 40 * 64 = 12800 floats (51.2KB)
    int tid = threadIdx.x;
    int b   = blockIdx.x >> 8;
    int ohp = blockIdx.x & 255;

    for (int i = tid; i < 12800; i += 512) {
        int r = i / 2560, rem = i - r * 2560;
        int h = 4 * ohp + r;
        sin_[i] = (h < 1024) ? g_x1[((size_t)b * 1024 + h) * 2560 + rem] : 0.f;
    }
    __syncthreads();

    int oc = tid & 63;
    int g  = tid >> 6;
    int wq = g & 3;
    int r2 = g >> 2;
    int oh = 2 * ohp + r2;

    unsigned long long acc1[5], acc2[5];
#pragma unroll
    for (int q = 0; q < 5; q++) {
        acc1[q] = pack2(b1[oc], 0.f);
        acc2[q] = pack2(b2[oc], 0.f);
    }

#pragma unroll
    for (int kh = 0; kh < 3; kh++) {
#pragma unroll
        for (int kw = 0; kw < 3; kw++) {
            int khkw = kh * 3 + kw;
            const unsigned long long* wr1 = g_wp1 + (size_t)khkw * 2048 + oc;
            const unsigned long long* wr2 = g_wp2 + (size_t)khkw * 2048 + oc;
            int off[5];
#pragma unroll
            for (int q = 0; q < 5; q++) {
                int w_in = 2 * (wq * 5 + q) + kw;
                off[q] = (w_in < 40) ? ((2 * r2 + kh) * 40 + w_in) * 64 : -1;
            }
#pragma unroll 8
            for (int ic2 = 0; ic2 < 32; ic2++) {
                unsigned long long wp1 = wr1[ic2 * 64];
                unsigned long long wp2 = wr2[ic2 * 64];
#pragma unroll
                for (int q = 0; q < 5; q++) {
                    if (off[q] >= 0) {
                        unsigned long long vv =
                            *reinterpret_cast<const unsigned long long*>(&sin_[off[q] + ic2 * 2]);
                        fma2(acc1[q], vv, wp1);
                        fma2(acc2[q], vv, wp2);
                    }
                }
            }
        }
    }

    int vl = (lens[b] + 3) >> 2;
    float mask = (oh < vl) ? 1.f : 0.f;
#pragma unroll
    for (int q = 0; q < 5; q++) {
        float2 f1 = unpack2(acc1[q]);
        float2 f2 = unpack2(acc2[q]);
        int ow = wq * 5 + q;
        g_x2[(((size_t)b * 512 + oh) * 20 + ow) * 64 + oc] =
            fmaxf(f1.x + f1.y, f2.x + f2.y) * mask;
    }
}

// ---------------- K3a: projection (packed k-pairs, 4 accumulator chains) ----------------
__global__ void __launch_bounds__(256) k_proj(const float* __restrict__ pb)
{
    __shared__ float sx[8 * 1280];  // 40KB
    int tid = threadIdx.x;
    int b  = blockIdx.x >> 6;
    int s0 = (blockIdx.x & 63) << 3;
    const float* src = &g_x2[((size_t)b * 512 + s0) * 1280];
    for (int i = tid; i < 10240; i += 256) sx[i] = src[i];
    __syncthreads();

    int col = tid & 31, sl = tid >> 5;
    unsigned long long acc[4];
    acc[0] = pack2(pb[col], 0.f);
    acc[1] = 0; acc[2] = 0; acc[3] = 0;
    const float* xr = &sx[sl * 1280];
    const unsigned long long* wp = g_pwp + col;
#pragma unroll 4
    for (int q = 0; q < 640; q += 4) {
#pragma unroll
        for (int j = 0; j < 4; j++) {
            unsigned long long xv =
                *reinterpret_cast<const unsigned long long*>(&xr[2 * (q + j)]);
            fma2(acc[j], xv, wp[(q + j) * 32]);
        }
    }
    float2 f0 = unpack2(acc[0]), f1 = unpack2(acc[1]);
    float2 f2 = unpack2(acc[2]), f3 = unpack2(acc[3]);
    g_p[((size_t)b * 512 + s0 + sl) * 32 + col] =
        (f0.x + f0.y) + (f1.x + f1.y) + (f2.x + f2.y) + (f3.x + f3.y);
}

// ---------------- K3b: encoder conv maxout + mask + squash + layernorm ----------------
__global__ void __launch_bounds__(256) k_enc(
    const float* __restrict__ ew1, const float* __restrict__ eb1,
    const float* __restrict__ ew2, const float* __restrict__ eb2,
    const int* __restrict__ lens)
{
    __shared__ float sp[3][32];
    __shared__ float sw[2][9][8];
    __shared__ float sbb[16];
    int tid = threadIdx.x;
    int p = blockIdx.x;
    int b = p >> 9, s = p & 511;

    if (tid < 96) {
        int j = tid >> 5, ii = tid & 31;
        int si = s + j - 1;
        sp[j][ii] = ((unsigned)si < 512u) ? g_p[((size_t)b * 512 + si) * 32 + ii] : 0.f;
    }
    if (tid < 72) { sw[0][tid / 8][tid & 7] = ew1[tid]; sw[1][tid / 8][tid & 7] = ew2[tid]; }
    if (tid < 16) sbb[tid] = (tid < 8) ? eb1[tid] : eb2[tid - 8];
    __syncthreads();

    int i = tid >> 3, d = tid & 7;
    float a1 = sbb[d], a2 = sbb[8 + d];
#pragma unroll
    for (int kh = 0; kh < 3; kh++)
#pragma unroll
        for (int kw = 0; kw < 3; kw++) {
            int ii = i + kw - 1;
            if ((unsigned)ii < 32u) {
                float v = sp[kh][ii];
                a1 = fmaf(v, sw[0][kh * 3 + kw][d], a1);
                a2 = fmaf(v, sw[1][kh * 3 + kw][d], a2);
            }
        }
    float e = fmaxf(a1, a2);
    int vl = (lens[b] + 3) >> 2;
    if (s >= vl) e = 0.f;

    float sq = e * e;
    sq += __shfl_xor_sync(0xffffffffu, sq, 1);
    sq += __shfl_xor_sync(0xffffffffu, sq, 2);
    sq += __shfl_xor_sync(0xffffffffu, sq, 4);
    float es = e * (sq / (1.f + sq) * rsqrtf(sq + 1e-6f));

    float a = es, b2 = es * es;
    blockReduceSum2(a, b2);
    float mu = a * (1.f / 256.f);
    float var = b2 * (1.f / 256.f) - mu * mu;
    g_emb[(size_t)p * 256 + tid] = (es - mu) * rsqrtf(var + 1e-3f);
}

// ---------------- K4a: u_hat GEMM -> fp16 (chunked; double-buffered) ----------------
template <int LAYER>
__global__ void __launch_bounds__(256) k_uhat(const float* __restrict__ Wt,
                                              const float* __restrict__ Bt,
                                              int pos_base, int buf)
{
    constexpr int O_REAL = LAYER ? 31 : 32;
    __shared__ float sW[64 * 32];   // [dk][o]
    __shared__ float sB[8 * 32];    // [d][o]
    __shared__ float sWin[64 * 8];  // [p_loc][k]
    const float* src = LAYER ? g_emb2 : g_emb;

    int tid = threadIdx.x;
    int i = blockIdx.y;
    int p0 = blockIdx.x * 64;       // local within chunk

    if (O_REAL < 32) {
        for (int t = tid; t < 64 * 32; t += 256) sW[t] = 0.f;
        sB[tid] = 0.f;
        __syncthreads();
    }
    for (int t = tid; t < O_REAL * 64; t += 256) {
        int o = t >> 6, dk = t & 63;
        sW[dk * 32 + o] = Wt[((size_t)i * O_REAL + o) * 64 + dk];
    }
    for (int t = tid; t < O_REAL * 8; t += 256) {
        int o = t >> 3, d = t & 7;
        sB[d * 32 + o] = Bt[((size_t)i * O_REAL + o) * 8 + d];
    }
    {
        int j = i >> 5, ii = i & 31;
        for (int t = tid; t < 512; t += 256) {
            int pl = t >> 3, k = t & 7;
            int pos = pos_base + p0 + pl;
            int b = pos >> 9, s = pos & 511;
            int sn = s + j - 1;
            sWin[t] = ((unsigned)sn < 512u)
                    ? src[(((size_t)b * 512 + sn) * 32 + ii) * 8 + k] : 0.f;
        }
    }
    __syncthreads();

    int o = tid & 31, grp = tid >> 5;
    float Wr[64];
#pragma unroll
    for (int dk = 0; dk < 64; dk++) Wr[dk] = sW[dk * 32 + o];
    float Br[8];
#pragma unroll
    for (int d = 0; d < 8; d++) Br[d] = sB[d * 32 + o];

    uint4* ub = g_ubuf[buf];
#pragma unroll
    for (int ps = 0; ps < 8; ps++) {
        int pl = grp * 8 + ps;
        float wk[8];
        *reinterpret_cast<float4*>(&wk[0]) = *reinterpret_cast<const float4*>(&sWin[pl * 8]);
        *reinterpret_cast<float4*>(&wk[4]) = *reinterpret_cast<const float4*>(&sWin[pl * 8 + 4]);
        float acc[8];
#pragma unroll
        for (int d = 0; d < 8; d++) {
            float a = Br[d];
#pragma unroll
            for (int k = 0; k < 8; k++) a = fmaf(Wr[d * 8 + k], wk[k], a);
            acc[d] = a;
        }
        size_t posl = (size_t)(p0 + pl);
        uint4 uv;
        uv.x = f2h(acc[0], acc[1]);
        uv.y = f2h(acc[2], acc[3]);
        uv.z = f2h(acc[4], acc[5]);
        uv.w = f2h(acc[6], acc[7]);
        ub[(posl * 96 + i) * 32 + o] = uv;
    }
}

// ---------------- K4b: dynamic routing (u fp16 in registers; chunked) ----------------
template <int LAYER>
__global__ void __launch_bounds__(256) k_route(float* __restrict__ out_final,
                                               int pos_base, int buf)
{
    constexpr int O_REAL = LAYER ? 31 : 32;
    __shared__ float sred[8 * 256];
    __shared__ float sv[256];
    __shared__ float slen[32];

    int tid = threadIdx.x;
    int pl = blockIdx.x;            // local within chunk
    int p  = pos_base + pl;         // global position
    int w = tid >> 5, o = tid & 31;

    unsigned uh[12][4];
    float bij[12];
    const uint4* up = &g_ubuf[buf][(((size_t)pl * 96 + w * 12) * 32 + o)];
#pragma unroll
    for (int jj = 0; jj < 12; jj++) {
        uint4 uv = up[jj * 32];
        uh[jj][0] = uv.x; uh[jj][1] = uv.y; uh[jj][2] = uv.z; uh[jj][3] = uv.w;
        bij[jj] = 0.f;
    }

    float mask = 0.f;
    if (LAYER == 1) { if (o == 0 || o >= O_REAL) mask = -1e9f; }

    int oo = tid >> 3, dd = tid & 7;
    float v_od = 0.f;

    for (int it = 0; it < 3; it++) {
        float sp8[8] = {0, 0, 0, 0, 0, 0, 0, 0};
#pragma unroll
        for (int jj = 0; jj < 12; jj++) {
            // softmax over o (lanes) without max-subtraction: logits bounded,
            // masked lanes exp(-1e9)=0 exactly.
            float e = __expf(bij[jj] + mask);
            float ssum = e;
#pragma unroll
            for (int off = 16; off; off >>= 1)
                ssum += __shfl_xor_sync(0xffffffffu, ssum, off);
            float c = __fdividef(e, ssum);
#pragma unroll
            for (int t = 0; t < 4; t++) {
                float2 f = h2f(uh[jj][t]);
                sp8[2 * t]     = fmaf(c, f.x, sp8[2 * t]);
                sp8[2 * t + 1] = fmaf(c, f.y, sp8[2 * t + 1]);
            }
        }
        *reinterpret_cast<float4*>(&sred[w * 256 + o * 8]) =
            make_float4(sp8[0], sp8[1], sp8[2], sp8[3]);
        *reinterpret_cast<float4*>(&sred[w * 256 + o * 8 + 4]) =
            make_float4(sp8[4], sp8[5], sp8[6], sp8[7]);
        __syncthreads();

        float s_od = 0.f;
#pragma unroll
        for (int w2 = 0; w2 < 8; w2++) s_od += sred[w2 * 256 + tid];
        float sq = s_od * s_od;
        sq += __shfl_xor_sync(0xffffffffu, sq, 1);
        sq += __shfl_xor_sync(0xffffffffu, sq, 2);
        sq += __shfl_xor_sync(0xffffffffu, sq, 4);
        v_od = s_od * (sq / (1.f + sq) * rsqrtf(sq + 1e-6f));
        sv[tid] = v_od;
        __syncthreads();

        if (it < 2) {
            float vv[8];
            *reinterpret_cast<float4*>(&vv[0]) = *reinterpret_cast<const float4*>(&sv[o * 8]);
            *reinterpret_cast<float4*>(&vv[4]) = *reinterpret_cast<const float4*>(&sv[o * 8 + 4]);
#pragma unroll
            for (int jj = 0; jj < 12; jj++) {
                float acc = 0.f;
#pragma unroll
                for (int t = 0; t < 4; t++) {
                    float2 f = h2f(uh[jj][t]);
                    acc = fmaf(f.x, vv[2 * t], acc);
                    acc = fmaf(f.y, vv[2 * t + 1], acc);
                }
                bij[jj] += acc;
            }
        }
    }

    if (LAYER == 0) {
        float a = v_od, b2 = v_od * v_od;
        blockReduceSum2(a, b2);
        float mu = a * (1.f / 256.f);
        float var = b2 * (1.f / 256.f) - mu * mu;
        g_emb2[(size_t)p * 256 + tid] = (v_od - mu) * rsqrtf(var + 1e-3f);
    } else {
        bool valid = (oo < O_REAL);
        float x = valid ? v_od : 0.f;
        float a = x, b2 = x * x;
        blockReduceSum2(a, b2);
        const float inv = 1.f / (float)(O_REAL * 8);
        float mu = a * inv;
        float var = b2 * inv - mu * mu;
        float vn = valid ? (x - mu) * rsqrtf(var + 1e-3f) : 0.f;
        float sq = vn * vn;
        sq += __shfl_xor_sync(0xffffffffu, sq, 1);
        sq += __shfl_xor_sync(0xffffffffu, sq, 2);
        sq += __shfl_xor_sync(0xffffffffu, sq, 4);
        if (dd == 0) slen[oo] = sqrtf(sq + 1e-6f);
        __syncthreads();
        if (tid < 32) {
            float l = (tid < O_REAL) ? slen[tid] : 0.f;
            float sa = l, sb = l * l;
#pragma unroll
            for (int off = 16; off; off >>= 1) {
                sa += __shfl_xor_sync(0xffffffffu, sa, off);
                sb += __shfl_xor_sync(0xffffffffu, sb, off);
            }
            float mu2 = sa / 31.f;
            float var2 = sb / 31.f - mu2 * mu2;
            if (tid < 31)
                out_final[(size_t)p * 31 + tid] = (l - mu2) * rsqrtf(var2 + 1e-3f);
        }
    }
}

// ---------------- launch ----------------
extern "C" void kernel_launch(void* const* d_in, const int* in_sizes, int n_in,
                              void* d_out, int out_size)
{
    (void)in_sizes; (void)n_in; (void)out_size;
    const float* inputs = (const float*)d_in[0];
    const float* c0w1 = (const float*)d_in[1];
    const float* c0b1 = (const float*)d_in[2];
    const float* c0w2 = (const float*)d_in[3];
    const float* c0b2 = (const float*)d_in[4];
    const float* c1w1 = (const float*)d_in[5];
    const float* c1b1 = (const float*)d_in[6];
    const float* c1w2 = (const float*)d_in[7];
    const float* c1b2 = (const float*)d_in[8];
    const float* pw   = (const float*)d_in[9];
    const float* pb   = (const float*)d_in[10];
    const float* ew1  = (const float*)d_in[11];
    const float* eb1  = (const float*)d_in[12];
    const float* ew2  = (const float*)d_in[13];
    const float* eb2  = (const float*)d_in[14];
    const float* W0   = (const float*)d_in[15];
    const float* B0   = (const float*)d_in[16];
    const float* W1   = (const float*)d_in[17];
    const float* B1   = (const float*)d_in[18];
    const int*   lens = (const int*)d_in[19];
    float* out = (float*)d_out;

    static cudaStream_t s2 = nullptr;
    static cudaEvent_t evFork = nullptr, evJoin = nullptr;
    if (!s2) {
        cudaStreamCreateWithFlags(&s2, cudaStreamNonBlocking);
        cudaEventCreateWithFlags(&evFork, cudaEventDisableTiming);
        cudaEventCreateWithFlags(&evJoin, cudaEventDisableTiming);
        cudaFuncSetAttribute(k_conv1, cudaFuncAttributeMaxDynamicSharedMemorySize, 52224);
    }

    k_prep<<<152, 256>>>(c1w1, c1w2, pw);
    k_conv0<<<2048, 256>>>(inputs, c0w1, c0b1, c0w2, c0b2, lens);
    k_conv1<<<2048, 512, 52224>>>(c1b1, c1b2, lens);
    k_proj<<<512, 256>>>(pb);
    k_enc<<<4096, 256>>>(ew1, eb1, ew2, eb2, lens);

    // fork: second stream waits for head pipeline
    cudaEventRecord(evFork, 0);
    cudaStreamWaitEvent(s2, evFork, 0);

    // two independent chunk chains, overlapped on two streams
    for (int c = 0; c < NCHUNK; c++) {
        int base = c * CHUNK;
        int buf = c & 1;
        cudaStream_t st = (c & 1) ? s2 : (cudaStream_t)0;
        k_uhat<0><<<dim3(CHUNK / 64, 96), 256, 0, st>>>(W0, B0, base, buf);
        k_route<0><<<CHUNK, 256, 0, st>>>(nullptr, base, buf);
        k_uhat<1><<<dim3(CHUNK / 64, 96), 256, 0, st>>>(W1, B1, base, buf);
        k_route<1><<<CHUNK, 256, 0, st>>>(out, base, buf);
    }

    // join
    cudaEventRecord(evJoin, s2);
    cudaStreamWaitEvent(0, evJoin, 0);
}

// round 8
// speedup vs baseline: 2.6451x; 1.0396x over previous
#include <cuda_runtime.h>
#include <cuda_bf16.h>
#include <cuda_fp16.h>
#include <cstdint>

// ---------------- scratch (device globals; no runtime allocation) ----------------
__device__ float g_x1[(size_t)8 * 1024 * 40 * 64];   // conv0 out [B,1024,40,64]
__device__ float g_x2[(size_t)8 * 512 * 20 * 64];    // conv1 out [B,512,20,64]
__device__ float g_p [(size_t)4096 * 32];            // proj out  [B*S,32]
__device__ float g_emb [(size_t)4096 * 256];         // primary caps [B*S,32,8]
__device__ float g_emb2[(size_t)4096 * 256];         // conv caps    [B*S,32,8]
__device__ uint4 g_ubuf[2][(size_t)1024 * 96 * 32];  // u_hat fp16 double buffer (2x50MB, L2-resident)
__device__ unsigned long long g_wp1[9 * 32 * 64];    // conv1 w1 packed (ic pairs)
__device__ unsigned long long g_wp2[9 * 32 * 64];    // conv1 w2 packed
__device__ unsigned long long g_pwp[640 * 32];       // proj w packed (k pairs)

#define CHUNK 1024
#define NCHUNK 4

// ---------------- helpers ----------------
__device__ __forceinline__ unsigned long long pack2(float x, float y) {
    unsigned long long r;
    asm("mov.b64 %0, {%1, %2};" : "=l"(r) : "f"(x), "f"(y));
    return r;
}
__device__ __forceinline__ void fma2(unsigned long long& c, unsigned long long a, unsigned long long b) {
    asm("fma.rn.f32x2 %0, %1, %2, %0;" : "+l"(c) : "l"(a), "l"(b));
}
__device__ __forceinline__ float2 unpack2(unsigned long long v) {
    float lo, hi;
    asm("mov.b64 {%0, %1}, %2;" : "=f"(lo), "=f"(hi) : "l"(v));
    return make_float2(lo, hi);
}
__device__ __forceinline__ float2 h2f(unsigned u) {
    __half2 h = *reinterpret_cast<__half2*>(&u);
    return __half22float2(h);
}
__device__ __forceinline__ unsigned f2h(float a, float b) {
    __half2 h = __floats2half2_rn(a, b);
    return *reinterpret_cast<unsigned*>(&h);
}

__device__ __forceinline__ void blockReduceSum2(float& a, float& b) {
    __shared__ float red[16];
    int lane = threadIdx.x & 31, w = threadIdx.x >> 5;
#pragma unroll
    for (int o = 16; o; o >>= 1) {
        a += __shfl_xor_sync(0xffffffffu, a, o);
        b += __shfl_xor_sync(0xffffffffu, b, o);
    }
    if (lane == 0) { red[w] = a; red[8 + w] = b; }
    __syncthreads();
    a = red[0] + red[1] + red[2] + red[3] + red[4] + red[5] + red[6] + red[7];
    b = red[8] + red[9] + red[10] + red[11] + red[12] + red[13] + red[14] + red[15];
    __syncthreads();
}

// ---------------- K0: weight pre-packing ----------------
__global__ void __launch_bounds__(256) k_prep(const float* __restrict__ w1,
                                              const float* __restrict__ w2,
                                              const float* __restrict__ pw)
{
    int idx = blockIdx.x * 256 + threadIdx.x;
    if (idx < 9 * 32 * 64) {
        int oc = idx & 63, r = idx >> 6;
        int khkw = r >> 5, ic2 = r & 31;
        int base = (khkw * 64 + ic2 * 2) * 64 + oc;
        g_wp1[idx] = pack2(w1[base], w1[base + 64]);
        g_wp2[idx] = pack2(w2[base], w2[base + 64]);
    }
    int pidx = idx - 9 * 32 * 64;
    if (pidx >= 0 && pidx < 640 * 32) {
        int col = pidx & 31, q = pidx >> 5;
        g_pwp[pidx] = pack2(pw[(2 * q) * 32 + col], pw[(2 * q + 1) * 32 + col]);
    }
}

// ---------------- K1: conv0 maxout + time mask (4 output rows per block) ----------------
__global__ void __launch_bounds__(256) k_conv0(
    const float* __restrict__ in,
    const float* __restrict__ w1, const float* __restrict__ b1,
    const float* __restrict__ w2, const float* __restrict__ b2,
    const int* __restrict__ lens)
{
    __shared__ float sw1[576], sw2[576], sb[128];
    __shared__ float sin_[9][80];
    int tid = threadIdx.x;
    int b   = blockIdx.x >> 8;
    int oh0 = (blockIdx.x & 255) << 2;
    int vl = (lens[b] + 1) >> 1;
    int c = tid & 63, owg = tid >> 6;

    if (oh0 >= vl) {  // whole block masked: write zeros, skip compute
#pragma unroll
        for (int r = 0; r < 4; r++) {
            float* dst = &g_x1[(((size_t)b * 1024 + oh0 + r) * 40) * 64 + c];
#pragma unroll
            for (int q = 0; q < 10; q++) dst[(size_t)(owg * 10 + q) * 64] = 0.f;
        }
        return;
    }

    for (int i = tid; i < 576; i += 256) { sw1[i] = w1[i]; sw2[i] = w2[i]; }
    if (tid < 64) { sb[tid] = b1[tid]; sb[64 + tid] = b2[tid]; }
    for (int i = tid; i < 720; i += 256) {
        int r = i / 80, w = i - r * 80;
        int h = 2 * oh0 + r;
        sin_[r][w] = (h < 2048) ? in[((size_t)b * 2048 + h) * 80 + w] : 0.f;
    }
    __syncthreads();

#pragma unroll
    for (int r = 0; r < 4; r++) {
        int oh = oh0 + r;
        float* dst = &g_x1[(((size_t)b * 1024 + oh) * 40) * 64 + c];
        if (oh < vl) {
#pragma unroll
            for (int q = 0; q < 10; q++) {
                int ow = owg * 10 + q;
                float a1 = sb[c], a2 = sb[64 + c];
#pragma unroll
                for (int kh = 0; kh < 3; kh++)
#pragma unroll
                    for (int kw = 0; kw < 3; kw++) {
                        int w_in = 2 * ow + kw;
                        if (w_in < 80) {
                            float v = sin_[2 * r + kh][w_in];
                            int wi = (kh * 3 + kw) * 64 + c;
                            a1 = fmaf(v, sw1[wi], a1);
                            a2 = fmaf(v, sw2[wi], a2);
                        }
                    }
                dst[(size_t)ow * 64] = fmaxf(a1, a2);
            }
        } else {
#pragma unroll
            for (int q = 0; q < 10; q++) dst[(size_t)(owg * 10 + q) * 64] = 0.f;
        }
    }
}

// ---------------- K2: conv1 maxout, 2 output rows per block (dynamic smem) ----------------
__global__ void __launch_bounds__(512) k_conv1(
    const float* __restrict__ b1, const float* __restrict__ b2,
    const int* __restrict__ lens)
{
    extern __shared__ float sin_[];  // 5 rows * 40 * 64 = 12800 floats (51.2KB)
    int tid = threadIdx.x;
    int b   = blockIdx.x >> 8;
    int ohp = blockIdx.x & 255;

    int vl = (lens[b] + 3) >> 2;
    int oc = tid & 63;
    int g  = tid >> 6;
    int wq = g & 3;
    int r2 = g >> 2;
    int oh = 2 * ohp + r2;

    if (2 * ohp >= vl) {  // both rows masked: zeros, skip everything
#pragma unroll
        for (int q = 0; q < 5; q++) {
            int ow = wq * 5 + q;
            g_x2[(((size_t)b * 512 + oh) * 20 + ow) * 64 + oc] = 0.f;
        }
        return;
    }

    for (int i = tid; i < 12800; i += 512) {
        int r = i / 2560, rem = i - r * 2560;
        int h = 4 * ohp + r;
        sin_[i] = (h < 1024) ? g_x1[((size_t)b * 1024 + h) * 2560 + rem] : 0.f;
    }
    __syncthreads();

    unsigned long long acc1[5], acc2[5];
#pragma unroll
    for (int q = 0; q < 5; q++) {
        acc1[q] = pack2(b1[oc], 0.f);
        acc2[q] = pack2(b2[oc], 0.f);
    }

#pragma unroll
    for (int kh = 0; kh < 3; kh++) {
#pragma unroll
        for (int kw = 0; kw < 3; kw++) {
            int khkw = kh * 3 + kw;
            const unsigned long long* wr1 = g_wp1 + (size_t)khkw * 2048 + oc;
            const unsigned long long* wr2 = g_wp2 + (size_t)khkw * 2048 + oc;
            int off[5];
#pragma unroll
            for (int q = 0; q < 5; q++) {
                int w_in = 2 * (wq * 5 + q) + kw;
                off[q] = (w_in < 40) ? ((2 * r2 + kh) * 40 + w_in) * 64 : -1;
            }
#pragma unroll 8
            for (int ic2 = 0; ic2 < 32; ic2++) {
                unsigned long long wp1 = wr1[ic2 * 64];
                unsigned long long wp2 = wr2[ic2 * 64];
#pragma unroll
                for (int q = 0; q < 5; q++) {
                    if (off[q] >= 0) {
                        unsigned long long vv =
                            *reinterpret_cast<const unsigned long long*>(&sin_[off[q] + ic2 * 2]);
                        fma2(acc1[q], vv, wp1);
                        fma2(acc2[q], vv, wp2);
                    }
                }
            }
        }
    }

    float mask = (oh < vl) ? 1.f : 0.f;
#pragma unroll
    for (int q = 0; q < 5; q++) {
        float2 f1 = unpack2(acc1[q]);
        float2 f2 = unpack2(acc2[q]);
        int ow = wq * 5 + q;
        g_x2[(((size_t)b * 512 + oh) * 20 + ow) * 64 + oc] =
            fmaxf(f1.x + f1.y, f2.x + f2.y) * mask;
    }
}

// ---------------- K3a: projection (packed k-pairs, 4 accumulator chains) ----------------
__global__ void __launch_bounds__(256) k_proj(const float* __restrict__ pb)
{
    __shared__ float sx[8 * 1280];  // 40KB
    int tid = threadIdx.x;
    int b  = blockIdx.x >> 6;
    int s0 = (blockIdx.x & 63) << 3;
    const float* src = &g_x2[((size_t)b * 512 + s0) * 1280];
    for (int i = tid; i < 10240; i += 256) sx[i] = src[i];
    __syncthreads();

    int col = tid & 31, sl = tid >> 5;
    unsigned long long acc[4];
    acc[0] = pack2(pb[col], 0.f);
    acc[1] = 0; acc[2] = 0; acc[3] = 0;
    const float* xr = &sx[sl * 1280];
    const unsigned long long* wp = g_pwp + col;
#pragma unroll 4
    for (int q = 0; q < 640; q += 4) {
#pragma unroll
        for (int j = 0; j < 4; j++) {
            unsigned long long xv =
                *reinterpret_cast<const unsigned long long*>(&xr[2 * (q + j)]);
            fma2(acc[j], xv, wp[(q + j) * 32]);
        }
    }
    float2 f0 = unpack2(acc[0]), f1 = unpack2(acc[1]);
    float2 f2 = unpack2(acc[2]), f3 = unpack2(acc[3]);
    g_p[((size_t)b * 512 + s0 + sl) * 32 + col] =
        (f0.x + f0.y) + (f1.x + f1.y) + (f2.x + f2.y) + (f3.x + f3.y);
}

// ---------------- K3b: encoder conv maxout + mask + squash + layernorm ----------------
__global__ void __launch_bounds__(256) k_enc(
    const float* __restrict__ ew1, const float* __restrict__ eb1,
    const float* __restrict__ ew2, const float* __restrict__ eb2,
    const int* __restrict__ lens)
{
    __shared__ float sp[3][32];
    __shared__ float sw[2][9][8];
    __shared__ float sbb[16];
    int tid = threadIdx.x;
    int p = blockIdx.x;
    int b = p >> 9, s = p & 511;

    if (tid < 96) {
        int j = tid >> 5, ii = tid & 31;
        int si = s + j - 1;
        sp[j][ii] = ((unsigned)si < 512u) ? g_p[((size_t)b * 512 + si) * 32 + ii] : 0.f;
    }
    if (tid < 72) { sw[0][tid / 8][tid & 7] = ew1[tid]; sw[1][tid / 8][tid & 7] = ew2[tid]; }
    if (tid < 16) sbb[tid] = (tid < 8) ? eb1[tid] : eb2[tid - 8];
    __syncthreads();

    int i = tid >> 3, d = tid & 7;
    float a1 = sbb[d], a2 = sbb[8 + d];
#pragma unroll
    for (int kh = 0; kh < 3; kh++)
#pragma unroll
        for (int kw = 0; kw < 3; kw++) {
            int ii = i + kw - 1;
            if ((unsigned)ii < 32u) {
                float v = sp[kh][ii];
                a1 = fmaf(v, sw[0][kh * 3 + kw][d], a1);
                a2 = fmaf(v, sw[1][kh * 3 + kw][d], a2);
            }
        }
    float e = fmaxf(a1, a2);
    int vl = (lens[b] + 3) >> 2;
    if (s >= vl) e = 0.f;

    float sq = e * e;
    sq += __shfl_xor_sync(0xffffffffu, sq, 1);
    sq += __shfl_xor_sync(0xffffffffu, sq, 2);
    sq += __shfl_xor_sync(0xffffffffu, sq, 4);
    float es = e * (sq / (1.f + sq) * rsqrtf(sq + 1e-6f));

    float a = es, b2 = es * es;
    blockReduceSum2(a, b2);
    float mu = a * (1.f / 256.f);
    float var = b2 * (1.f / 256.f) - mu * mu;
    g_emb[(size_t)p * 256 + tid] = (es - mu) * rsqrtf(var + 1e-3f);
}

// ---------------- K4a: u_hat GEMM -> fp16 (chunked; double-buffered) ----------------
template <int LAYER>
__global__ void __launch_bounds__(256) k_uhat(const float* __restrict__ Wt,
                                              const float* __restrict__ Bt,
                                              int pos_base, int buf)
{
    constexpr int O_REAL = LAYER ? 31 : 32;
    __shared__ float sW[64 * 32];   // [dk][o]
    __shared__ float sB[8 * 32];    // [d][o]
    __shared__ float sWin[64 * 8];  // [p_loc][k]
    const float* src = LAYER ? g_emb2 : g_emb;

    int tid = threadIdx.x;
    int i = blockIdx.y;
    int p0 = blockIdx.x * 64;       // local within chunk

    if (O_REAL < 32) {
        for (int t = tid; t < 64 * 32; t += 256) sW[t] = 0.f;
        sB[tid] = 0.f;
        __syncthreads();
    }
    for (int t = tid; t < O_REAL * 64; t += 256) {
        int o = t >> 6, dk = t & 63;
        sW[dk * 32 + o] = Wt[((size_t)i * O_REAL + o) * 64 + dk];
    }
    for (int t = tid; t < O_REAL * 8; t += 256) {
        int o = t >> 3, d = t & 7;
        sB[d * 32 + o] = Bt[((size_t)i * O_REAL + o) * 8 + d];
    }
    {
        int j = i >> 5, ii = i & 31;
        for (int t = tid; t < 512; t += 256) {
            int pl = t >> 3, k = t & 7;
            int pos = pos_base + p0 + pl;
            int b = pos >> 9, s = pos & 511;
            int sn = s + j - 1;
            sWin[t] = ((unsigned)sn < 512u)
                    ? src[(((size_t)b * 512 + sn) * 32 + ii) * 8 + k] : 0.f;
        }
    }
    __syncthreads();

    int o = tid & 31, grp = tid >> 5;
    float Wr[64];
#pragma unroll
    for (int dk = 0; dk < 64; dk++) Wr[dk] = sW[dk * 32 + o];
    float Br[8];
#pragma unroll
    for (int d = 0; d < 8; d++) Br[d] = sB[d * 32 + o];

    uint4* ub = g_ubuf[buf];
#pragma unroll
    for (int ps = 0; ps < 8; ps++) {
        int pl = grp * 8 + ps;
        float wk[8];
        *reinterpret_cast<float4*>(&wk[0]) = *reinterpret_cast<const float4*>(&sWin[pl * 8]);
        *reinterpret_cast<float4*>(&wk[4]) = *reinterpret_cast<const float4*>(&sWin[pl * 8 + 4]);
        float acc[8];
#pragma unroll
        for (int d = 0; d < 8; d++) {
            float a = Br[d];
#pragma unroll
            for (int k = 0; k < 8; k++) a = fmaf(Wr[d * 8 + k], wk[k], a);
            acc[d] = a;
        }
        size_t posl = (size_t)(p0 + pl);
        uint4 uv;
        uv.x = f2h(acc[0], acc[1]);
        uv.y = f2h(acc[2], acc[3]);
        uv.z = f2h(acc[4], acc[5]);
        uv.w = f2h(acc[6], acc[7]);
        ub[(posl * 96 + i) * 32 + o] = uv;
    }
}

// ---------------- K4b: dynamic routing (u fp16 in registers; chunked) ----------------
template <int LAYER>
__global__ void __launch_bounds__(256) k_route(float* __restrict__ out_final,
                                               int pos_base, int buf)
{
    constexpr int O_REAL = LAYER ? 31 : 32;
    __shared__ float sred[8 * 256];
    __shared__ float sv[256];
    __shared__ float slen[32];

    int tid = threadIdx.x;
    int pl = blockIdx.x;            // local within chunk
    int p  = pos_base + pl;         // global position
    int w = tid >> 5, o = tid & 31;

    unsigned uh[12][4];
    float bij[12];
    const uint4* up = &g_ubuf[buf][(((size_t)pl * 96 + w * 12) * 32 + o)];
#pragma unroll
    for (int jj = 0; jj < 12; jj++) {
        uint4 uv = up[jj * 32];
        uh[jj][0] = uv.x; uh[jj][1] = uv.y; uh[jj][2] = uv.z; uh[jj][3] = uv.w;
        bij[jj] = 0.f;
    }

    float mask = 0.f;
    if (LAYER == 1) { if (o == 0 || o >= O_REAL) mask = -1e9f; }

    int oo = tid >> 3, dd = tid & 7;
    float v_od = 0.f;

    for (int it = 0; it < 3; it++) {
        float sp8[8] = {0, 0, 0, 0, 0, 0, 0, 0};
#pragma unroll
        for (int jj = 0; jj < 12; jj++) {
            float e = __expf(bij[jj] + mask);
            float ssum = e;
#pragma unroll
            for (int off = 16; off; off >>= 1)
                ssum += __shfl_xor_sync(0xffffffffu, ssum, off);
            float c = __fdividef(e, ssum);
#pragma unroll
            for (int t = 0; t < 4; t++) {
                float2 f = h2f(uh[jj][t]);
                sp8[2 * t]     = fmaf(c, f.x, sp8[2 * t]);
                sp8[2 * t + 1] = fmaf(c, f.y, sp8[2 * t + 1]);
            }
        }
        *reinterpret_cast<float4*>(&sred[w * 256 + o * 8]) =
            make_float4(sp8[0], sp8[1], sp8[2], sp8[3]);
        *reinterpret_cast<float4*>(&sred[w * 256 + o * 8 + 4]) =
            make_float4(sp8[4], sp8[5], sp8[6], sp8[7]);
        __syncthreads();

        float s_od = 0.f;
#pragma unroll
        for (int w2 = 0; w2 < 8; w2++) s_od += sred[w2 * 256 + tid];
        float sq = s_od * s_od;
        sq += __shfl_xor_sync(0xffffffffu, sq, 1);
        sq += __shfl_xor_sync(0xffffffffu, sq, 2);
        sq += __shfl_xor_sync(0xffffffffu, sq, 4);
        v_od = s_od * (sq / (1.f + sq) * rsqrtf(sq + 1e-6f));
        sv[tid] = v_od;
        __syncthreads();

        if (it < 2) {
            float vv[8];
            *reinterpret_cast<float4*>(&vv[0]) = *reinterpret_cast<const float4*>(&sv[o * 8]);
            *reinterpret_cast<float4*>(&vv[4]) = *reinterpret_cast<const float4*>(&sv[o * 8 + 4]);
#pragma unroll
            for (int jj = 0; jj < 12; jj++) {
                float acc = 0.f;
#pragma unroll
                for (int t = 0; t < 4; t++) {
                    float2 f = h2f(uh[jj][t]);
                    acc = fmaf(f.x, vv[2 * t], acc);
                    acc = fmaf(f.y, vv[2 * t + 1], acc);
                }
                bij[jj] += acc;
            }
        }
    }

    if (LAYER == 0) {
        float a = v_od, b2 = v_od * v_od;
        blockReduceSum2(a, b2);
        float mu = a * (1.f / 256.f);
        float var = b2 * (1.f / 256.f) - mu * mu;
        g_emb2[(size_t)p * 256 + tid] = (v_od - mu) * rsqrtf(var + 1e-3f);
    } else {
        bool valid = (oo < O_REAL);
        float x = valid ? v_od : 0.f;
        float a = x, b2 = x * x;
        blockReduceSum2(a, b2);
        const float inv = 1.f / (float)(O_REAL * 8);
        float mu = a * inv;
        float var = b2 * inv - mu * mu;
        float vn = valid ? (x - mu) * rsqrtf(var + 1e-3f) : 0.f;
        float sq = vn * vn;
        sq += __shfl_xor_sync(0xffffffffu, sq, 1);
        sq += __shfl_xor_sync(0xffffffffu, sq, 2);
        sq += __shfl_xor_sync(0xffffffffu, sq, 4);
        if (dd == 0) slen[oo] = sqrtf(sq + 1e-6f);
        __syncthreads();
        if (tid < 32) {
            float l = (tid < O_REAL) ? slen[tid] : 0.f;
            float sa = l, sb = l * l;
#pragma unroll
            for (int off = 16; off; off >>= 1) {
                sa += __shfl_xor_sync(0xffffffffu, sa, off);
                sb += __shfl_xor_sync(0xffffffffu, sb, off);
            }
            float mu2 = sa / 31.f;
            float var2 = sb / 31.f - mu2 * mu2;
            if (tid < 31)
                out_final[(size_t)p * 31 + tid] = (l - mu2) * rsqrtf(var2 + 1e-3f);
        }
    }
}

// ---------------- launch ----------------
extern "C" void kernel_launch(void* const* d_in, const int* in_sizes, int n_in,
                              void* d_out, int out_size)
{
    (void)in_sizes; (void)n_in; (void)out_size;
    const float* inputs = (const float*)d_in[0];
    const float* c0w1 = (const float*)d_in[1];
    const float* c0b1 = (const float*)d_in[2];
    const float* c0w2 = (const float*)d_in[3];
    const float* c0b2 = (const float*)d_in[4];
    const float* c1w1 = (const float*)d_in[5];
    const float* c1b1 = (const float*)d_in[6];
    const float* c1w2 = (const float*)d_in[7];
    const float* c1b2 = (const float*)d_in[8];
    const float* pw   = (const float*)d_in[9];
    const float* pb   = (const float*)d_in[10];
    const float* ew1  = (const float*)d_in[11];
    const float* eb1  = (const float*)d_in[12];
    const float* ew2  = (const float*)d_in[13];
    const float* eb2  = (const float*)d_in[14];
    const float* W0   = (const float*)d_in[15];
    const float* B0   = (const float*)d_in[16];
    const float* W1   = (const float*)d_in[17];
    const float* B1   = (const float*)d_in[18];
    const int*   lens = (const int*)d_in[19];
    float* out = (float*)d_out;

    static cudaStream_t s2 = nullptr;
    static cudaEvent_t evFork = nullptr, evJoin = nullptr;
    if (!s2) {
        cudaStreamCreateWithFlags(&s2, cudaStreamNonBlocking);
        cudaEventCreateWithFlags(&evFork, cudaEventDisableTiming);
        cudaEventCreateWithFlags(&evJoin, cudaEventDisableTiming);
        cudaFuncSetAttribute(k_conv1, cudaFuncAttributeMaxDynamicSharedMemorySize, 52224);
    }

    // head pipeline on the launch (capture) stream
    k_prep<<<152, 256>>>(c1w1, c1w2, pw);
    k_conv0<<<2048, 256>>>(inputs, c0w1, c0b1, c0w2, c0b2, lens);
    k_conv1<<<2048, 512, 52224>>>(c1b1, c1b2, lens);
    k_proj<<<512, 256>>>(pb);
    k_enc<<<4096, 256>>>(ew1, eb1, ew2, eb2, lens);

    // fork: second stream waits for head pipeline
    cudaEventRecord(evFork, 0);
    cudaStreamWaitEvent(s2, evFork, 0);

    // two independent chunk chains, overlapped on two streams
    for (int c = 0; c < NCHUNK; c++) {
        int base = c * CHUNK;
        int buf = c & 1;
        cudaStream_t st = (c & 1) ? s2 : (cudaStream_t)0;
        k_uhat<0><<<dim3(CHUNK / 64, 96), 256, 0, st>>>(W0, B0, base, buf);
        k_route<0><<<CHUNK, 256, 0, st>>>(nullptr, base, buf);
        k_uhat<1><<<dim3(CHUNK / 64, 96), 256, 0, st>>>(W1, B1, base, buf);
        k_route<1><<<CHUNK, 256, 0, st>>>(out, base, buf);
    }

    // join
    cudaEventRecord(evJoin, s2);
    cudaStreamWaitEvent(0, evJoin, 0);
}